// round 8
// baseline (speedup 1.0000x reference)
#include <cuda_runtime.h>
#include <cuda_bf16.h>

#define NTHREADS 256

struct Params { const float* p[24]; };

// ---- scratch (static device globals; no allocation) ----
__device__ float g_keys   [64*64*128];
__device__ float g_queries[64*64*128];
__device__ float g_hk     [64*64*128];
__device__ float g_hq     [64*64*128];
__device__ float g_attn   [64*64*64];
__device__ float g_asum   [64*64];
__device__ float g_G      [64*64*128];
// Wv2^T as [n=s_out][k=s_in], bf16 hi/lo, rows padded to 136 elems (272B)
__device__ __align__(16) unsigned short g_Whi[128*136];
__device__ __align__(16) unsigned short g_Wlo[128*136];

__device__ __forceinline__ float tanha(float x) {
    float y;
    asm("tanh.approx.f32 %0, %1;" : "=f"(y) : "f"(x));
    return y;
}

__device__ __forceinline__ void cp4(float* dst, const float* src, int n, int t) {
    for (int i = t*4; i < n; i += NTHREADS*4)
        *reinterpret_cast<float4*>(dst + i) = *reinterpret_cast<const float4*>(src + i);
}

__device__ __forceinline__ int colidx(int tx, int j) { return j < 4 ? tx*4 + j : 60 + tx*4 + j; }

__device__ __forceinline__ void zero_acc8(float acc[4][8]) {
    #pragma unroll
    for (int i = 0; i < 4; ++i)
        #pragma unroll
        for (int j = 0; j < 8; ++j) acc[i][j] = 0.f;
}

template<int K>
__device__ __forceinline__ void gemm_tile(const float* __restrict__ A, const float* __restrict__ W,
                                          float acc[4][8], int tx, int ty) {
    const int r0 = ty * 4;
    const int ca = tx * 4, cb = 64 + tx * 4;
    #pragma unroll 4
    for (int k = 0; k < K; ++k) {
        float aa[4];
        #pragma unroll
        for (int i = 0; i < 4; ++i) aa[i] = A[(r0 + i) * K + k];
        float4 b0 = *reinterpret_cast<const float4*>(W + k * 128 + ca);
        float4 b1 = *reinterpret_cast<const float4*>(W + k * 128 + cb);
        float bb[8] = {b0.x, b0.y, b0.z, b0.w, b1.x, b1.y, b1.z, b1.w};
        #pragma unroll
        for (int i = 0; i < 4; ++i)
            #pragma unroll
            for (int j = 0; j < 8; ++j)
                acc[i][j] = fmaf(aa[i], bb[j], acc[i][j]);
    }
}

__device__ __forceinline__ void store_row4(float* base, int row, int tx, const float v[8]) {
    *reinterpret_cast<float4*>(base + row * 128 + tx * 4)      = make_float4(v[0], v[1], v[2], v[3]);
    *reinterpret_cast<float4*>(base + row * 128 + 64 + tx * 4) = make_float4(v[4], v[5], v[6], v[7]);
}

__device__ __forceinline__ unsigned smem_u32(const void* p) {
    unsigned a;
    asm("{ .reg .u64 t; cvta.to.shared.u64 t, %1; cvt.u32.u64 %0, t; }" : "=r"(a) : "l"(p));
    return a;
}

#define LDSM_X4(r, addr)                                                       \
    asm volatile("ldmatrix.sync.aligned.m8n8.x4.shared.b16 {%0,%1,%2,%3}, [%4];" \
        : "=r"((r)[0]), "=r"((r)[1]), "=r"((r)[2]), "=r"((r)[3]) : "r"(addr))

#define MMA16816(d, a, b0, b1)                                                 \
    asm volatile("mma.sync.aligned.m16n8k16.row.col.f32.bf16.bf16.f32 "        \
        "{%0,%1,%2,%3}, {%4,%5,%6,%7}, {%8,%9}, {%0,%1,%2,%3};"                \
        : "+f"((d)[0]), "+f"((d)[1]), "+f"((d)[2]), "+f"((d)[3])               \
        : "r"((a)[0]), "r"((a)[1]), "r"((a)[2]), "r"((a)[3]), "r"(b0), "r"(b1))

// =====================================================================
// Kernel kW: precompute Wv2^T bf16 hi/lo into padded [128][136]. grid 64
// =====================================================================
__global__ __launch_bounds__(256) void kW(Params P) {
    int t = blockIdx.x * 256 + threadIdx.x;
    const float* Wv2 = P.p[14];
    if (t < 16384) {
        int n = t >> 7, k = t & 127;
        float v = Wv2[k * 128 + n];
        __nv_bfloat16 hb = __float2bfloat16(v);
        __nv_bfloat16 lb = __float2bfloat16(v - __bfloat162float(hb));
        g_Whi[n * 136 + k] = __bfloat16_as_ushort(hb);
        g_Wlo[n * 136 + k] = __bfloat16_as_ushort(lb);
    }
}

// =====================================================================
// Kernel A1: keys / queries MLPs + hk, hq projections. grid (64 bc, 2 paths)
// =====================================================================
__global__ __launch_bounds__(256) void kA1(Params P) {
    extern __shared__ float sm[];
    float* X  = sm;
    float* W  = sm + 6144;
    float* T1 = W + 16384;
    float* T2 = T1 + 8192;
    const int t = threadIdx.x, tx = t & 15, ty = t >> 4;
    const int bc = blockIdx.x;
    const int r0 = ty * 4;
    float acc[4][8];

    if (blockIdx.y == 0) {
        cp4(X, P.p[0] + bc * 6144, 6144, t);
        cp4(W, P.p[2], 12288, t);
        __syncthreads();
        zero_acc8(acc);
        gemm_tile<96>(X, W, acc, tx, ty);
        {
            const float aK = P.p[18][0];
            const float* bk1 = P.p[3];
            #pragma unroll
            for (int i = 0; i < 4; ++i) {
                float v[8];
                #pragma unroll
                for (int j = 0; j < 8; ++j) {
                    int c = colidx(tx, j);
                    float x = acc[i][j] + bk1[c];
                    v[j] = x >= 0.f ? x : aK * x;
                }
                store_row4(T1, r0 + i, tx, v);
            }
        }
        __syncthreads();
        cp4(W, P.p[4], 16384, t);
        __syncthreads();
        zero_acc8(acc);
        gemm_tile<128>(T1, W, acc, tx, ty);
        {
            const float* bk2 = P.p[5];
            const float* gK  = P.p[20];
            const float* beK = P.p[21];
            #pragma unroll
            for (int i = 0; i < 4; ++i) {
                float v[8]; float s1 = 0.f, s2 = 0.f;
                #pragma unroll
                for (int j = 0; j < 8; ++j) {
                    int c = colidx(tx, j);
                    float x = tanha(acc[i][j] + bk2[c]);
                    v[j] = x; s1 += x; s2 += x * x;
                }
                #pragma unroll
                for (int off = 8; off >= 1; off >>= 1) {
                    s1 += __shfl_xor_sync(0xffffffffu, s1, off);
                    s2 += __shfl_xor_sync(0xffffffffu, s2, off);
                }
                float m  = s1 * (1.f / 128.f);
                float va = s2 * (1.f / 128.f) - m * m;
                float rs = rsqrtf(va + 1e-5f);
                #pragma unroll
                for (int j = 0; j < 8; ++j) {
                    int c = colidx(tx, j);
                    v[j] = (v[j] - m) * rs * gK[c] + beK[c];
                }
                store_row4(T2, r0 + i, tx, v);
            }
        }
        __syncthreads();
        cp4(W, P.p[6], 16384, t);
        __syncthreads();
        zero_acc8(acc);
        gemm_tile<128>(T2, W, acc, tx, ty);
        {
            const float* bk3 = P.p[7];
            float* kout = g_keys + bc * 8192;
            #pragma unroll
            for (int i = 0; i < 4; ++i) {
                float v[8];
                #pragma unroll
                for (int j = 0; j < 8; ++j) v[j] = acc[i][j] + bk3[colidx(tx, j)];
                store_row4(T1, r0 + i, tx, v);
                store_row4(kout, r0 + i, tx, v);
            }
        }
        __syncthreads();
        cp4(W, P.p[12] + 16384, 16384, t);
        __syncthreads();
        zero_acc8(acc);
        gemm_tile<128>(T1, W, acc, tx, ty);
        {
            float* hkout = g_hk + bc * 8192;
            #pragma unroll
            for (int i = 0; i < 4; ++i) {
                float v[8];
                #pragma unroll
                for (int j = 0; j < 8; ++j) v[j] = acc[i][j];
                store_row4(hkout, r0 + i, tx, v);
            }
        }
    } else {
        cp4(X, P.p[1] + bc * 6144, 6144, t);
        cp4(W, P.p[8], 12288, t);
        __syncthreads();
        zero_acc8(acc);
        gemm_tile<96>(X, W, acc, tx, ty);
        {
            const float* bq1 = P.p[9];
            #pragma unroll
            for (int i = 0; i < 4; ++i) {
                float v[8];
                #pragma unroll
                for (int j = 0; j < 8; ++j) v[j] = tanha(acc[i][j] + bq1[colidx(tx, j)]);
                store_row4(T1, r0 + i, tx, v);
            }
        }
        __syncthreads();
        cp4(W, P.p[10], 16384, t);
        __syncthreads();
        zero_acc8(acc);
        gemm_tile<128>(T1, W, acc, tx, ty);
        {
            const float* bq2 = P.p[11];
            float* qout = g_queries + bc * 8192;
            #pragma unroll
            for (int i = 0; i < 4; ++i) {
                float v[8];
                #pragma unroll
                for (int j = 0; j < 8; ++j) v[j] = acc[i][j] + bq2[colidx(tx, j)];
                store_row4(T2, r0 + i, tx, v);
                store_row4(qout, r0 + i, tx, v);
            }
        }
        __syncthreads();
        cp4(W, P.p[12], 16384, t);
        __syncthreads();
        zero_acc8(acc);
        gemm_tile<128>(T2, W, acc, tx, ty);
        {
            float* hqout = g_hq + bc * 8192;
            #pragma unroll
            for (int i = 0; i < 4; ++i) {
                float v[8];
                #pragma unroll
                for (int j = 0; j < 8; ++j) v[j] = acc[i][j];
                store_row4(hqout, r0 + i, tx, v);
            }
        }
    }
}

// =====================================================================
// Kernel A2: logits + softmax over n (axis 2) + attn row sums. grid 64
// =====================================================================
__global__ __launch_bounds__(256) void kA2(Params P) {
    extern __shared__ float sm[];
    float* Kp = sm;
    float* Q  = sm + 8256;
    float* L  = Q + 8256;
    const int t = threadIdx.x, tx = t & 15, ty = t >> 4;
    const int bc = blockIdx.x;

    for (int i = t; i < 8192; i += NTHREADS) {
        int r = i >> 7, c = i & 127;
        Kp[r * 129 + c] = g_keys[bc * 8192 + i];
        Q [r * 129 + c] = g_queries[bc * 8192 + i];
    }
    __syncthreads();

    float acc[4][4];
    #pragma unroll
    for (int i = 0; i < 4; ++i)
        #pragma unroll
        for (int j = 0; j < 4; ++j) acc[i][j] = 0.f;
    #pragma unroll 4
    for (int k = 0; k < 128; ++k) {
        float a[4], b[4];
        #pragma unroll
        for (int i = 0; i < 4; ++i) a[i] = Kp[(ty * 4 + i) * 129 + k];
        #pragma unroll
        for (int j = 0; j < 4; ++j) b[j] = Q[(tx * 4 + j) * 129 + k];
        #pragma unroll
        for (int i = 0; i < 4; ++i)
            #pragma unroll
            for (int j = 0; j < 4; ++j) acc[i][j] = fmaf(a[i], b[j], acc[i][j]);
    }
    #pragma unroll
    for (int i = 0; i < 4; ++i)
        #pragma unroll
        for (int j = 0; j < 4; ++j) L[(ty * 4 + i) * 65 + tx * 4 + j] = acc[i][j];
    __syncthreads();

    if (t < 64) {
        int m = t;
        float mx = -1e30f;
        for (int n = 0; n < 64; ++n) mx = fmaxf(mx, L[n * 65 + m]);
        float s = 0.f;
        for (int n = 0; n < 64; ++n) { float e = expf(L[n * 65 + m] - mx); L[n * 65 + m] = e; s += e; }
        float inv = 1.f / s;
        for (int n = 0; n < 64; ++n) L[n * 65 + m] *= inv;
    }
    __syncthreads();
    if (t < 64) {
        int n = t; float s = 0.f;
        for (int m = 0; m < 64; ++m) {
            float v = L[n * 65 + m];
            g_attn[bc * 4096 + n * 64 + m] = v;
            s += v;
        }
        g_asum[bc * 64 + n] = s;
    }
}

// =====================================================================
// Kernel B (persistent HMMA, 256 thr, 8 warps x 32m x 128n): grid 148.
// Unit = (bc, n-quad): A = 256 rows (4 n x 64 m) bf16 hi/lo; each warp
// owns 32 rows, reuses B fragments across 2 A fragments -> LDSM/MMA 0.21.
// =====================================================================
// byte offsets within dynamic smem
#define KB_WHI    0u
#define KB_WLO    34816u
#define KB_AHI    69632u           // 256 rows x 272 B
#define KB_ALO    139264u
#define KB_CONST  208896u          // bv1s, bv2s, gvs, bevs (128 floats each)
#define KB_MISC   210944u          // arow(1024B) hkn(2048B) red(4096B)
#define KB_SMEM_BYTES 218112

__global__ __launch_bounds__(256, 1) void kB(Params P) {
    extern __shared__ char smc[];
    const int t = threadIdx.x;
    const int w = t >> 5, l = t & 31;

    float* bv1s = reinterpret_cast<float*>(smc + KB_CONST);
    float* bv2s = bv1s + 128;
    float* gvs  = bv2s + 128;
    float* bevs = gvs + 128;
    float* arow = reinterpret_cast<float*>(smc + KB_MISC);  // 256
    float* hkn  = arow + 256;                               // 512
    float* red  = hkn + 512;                                // 8 x 128

    unsigned short* Ahi = reinterpret_cast<unsigned short*>(smc + KB_AHI);
    unsigned short* Alo = reinterpret_cast<unsigned short*>(smc + KB_ALO);

    // ---- one-time staging: W hi/lo + const vectors ----
    {
        const float4* s0 = reinterpret_cast<const float4*>(g_Whi);
        const float4* s1 = reinterpret_cast<const float4*>(g_Wlo);
        float4* d0 = reinterpret_cast<float4*>(smc + KB_WHI);
        float4* d1 = reinterpret_cast<float4*>(smc + KB_WLO);
        for (int i = t; i < 2176; i += 256) { d0[i] = s0[i]; d1[i] = s1[i]; }
        if (t < 128) {
            bv1s[t] = P.p[13][t];
            bv2s[t] = P.p[15][t];
            gvs[t]  = P.p[22][t];
            bevs[t] = P.p[23][t];
        }
    }
    __syncthreads();

    const float aV = P.p[19][0];
    const unsigned sbase = smem_u32(smc);
    // A: warp rows w*32..+31; two 16-row ldmatrix fragment bases
    const unsigned aAddr0 = sbase + KB_AHI + ((w * 32 + (l & 15)) * 136) * 2 + (l >> 4) * 16;
    const unsigned aAddr1 = aAddr0 + 16 * 272;
    const unsigned ALO_D  = KB_ALO - KB_AHI;   // 69632
    // B: full 128 cols per warp; p in 0..7 steps 16 cols (4352 B)
    const unsigned bRow = (l & 7) + ((l >> 4) & 1) * 8;
    const unsigned bHiAddr = sbase + KB_WHI + (bRow * 136) * 2 + ((l >> 3) & 1) * 16;
    const unsigned bLoAddr = bHiAddr + 34816;

    const int qr = l >> 2, qc = l & 3;

    for (int unit = blockIdx.x; unit < 1024; unit += 148) {
        const int bc = unit >> 4;
        const int n0 = (unit & 15) * 4;

        // ---- per-unit staging: attn rows (4n x 64m) + hk rows (4 x 128) ----
        arow[t] = g_attn[bc * 4096 + n0 * 64 + t];
        hkn[t]       = g_hk[(bc * 64 + n0) * 128 + t];
        hkn[t + 256] = g_hk[(bc * 64 + n0) * 128 + t + 256];
        __syncthreads();

        // ---- build A tile: thread t builds row t (nl = t>>6, m = t&63) ----
        {
            const int m = t & 63, nl = t >> 6;
            const float* hq = g_hq + bc * 8192 + m * 128;
            const float* hk = hkn + nl * 128;
            unsigned short* ph = Ahi + t * 136;
            unsigned short* pl = Alo + t * 136;
            #pragma unroll 4
            for (int j = 0; j < 32; ++j) {
                float4 h  = *reinterpret_cast<const float4*>(hq + j * 4);
                float4 kk = *reinterpret_cast<const float4*>(hk + j * 4);
                float4 bb = *reinterpret_cast<const float4*>(bv1s + j * 4);
                float a0 = h.x + kk.x + bb.x; a0 = a0 >= 0.f ? a0 : aV * a0;
                float a1 = h.y + kk.y + bb.y; a1 = a1 >= 0.f ? a1 : aV * a1;
                float a2 = h.z + kk.z + bb.z; a2 = a2 >= 0.f ? a2 : aV * a2;
                float a3 = h.w + kk.w + bb.w; a3 = a3 >= 0.f ? a3 : aV * a3;
                __nv_bfloat16 h0 = __float2bfloat16(a0), h1 = __float2bfloat16(a1);
                __nv_bfloat16 h2 = __float2bfloat16(a2), h3 = __float2bfloat16(a3);
                __nv_bfloat16 l0 = __float2bfloat16(a0 - __bfloat162float(h0));
                __nv_bfloat16 l1 = __float2bfloat16(a1 - __bfloat162float(h1));
                __nv_bfloat16 l2 = __float2bfloat16(a2 - __bfloat162float(h2));
                __nv_bfloat16 l3 = __float2bfloat16(a3 - __bfloat162float(h3));
                uint2 vh, vl;
                vh.x = (unsigned)__bfloat16_as_ushort(h0) | ((unsigned)__bfloat16_as_ushort(h1) << 16);
                vh.y = (unsigned)__bfloat16_as_ushort(h2) | ((unsigned)__bfloat16_as_ushort(h3) << 16);
                vl.x = (unsigned)__bfloat16_as_ushort(l0) | ((unsigned)__bfloat16_as_ushort(l1) << 16);
                vl.y = (unsigned)__bfloat16_as_ushort(l2) | ((unsigned)__bfloat16_as_ushort(l3) << 16);
                *reinterpret_cast<uint2*>(ph + j * 4) = vh;
                *reinterpret_cast<uint2*>(pl + j * 4) = vl;
            }
        }
        __syncthreads();

        // ---- GEMM: warp = 32m x 128n, K=128, 3 chains ----
        float acc[2][16][4];
        #pragma unroll
        for (int f = 0; f < 2; ++f)
            #pragma unroll
            for (int nt = 0; nt < 16; ++nt)
                #pragma unroll
                for (int j = 0; j < 4; ++j) acc[f][nt][j] = 0.f;

        #pragma unroll
        for (int ks = 0; ks < 8; ++ks) {
            unsigned ah0[4], ah1[4], al0[4], al1[4];
            LDSM_X4(ah0, aAddr0 + ks * 32);
            LDSM_X4(ah1, aAddr1 + ks * 32);
            LDSM_X4(al0, aAddr0 + ALO_D + ks * 32);
            LDSM_X4(al1, aAddr1 + ALO_D + ks * 32);
            #pragma unroll
            for (int p = 0; p < 8; ++p) {
                unsigned bh[4], bl[4];
                LDSM_X4(bh, bHiAddr + p * 4352 + ks * 32);
                LDSM_X4(bl, bLoAddr + p * 4352 + ks * 32);
                MMA16816(acc[0][2*p],     ah0, bh[0], bh[1]);
                MMA16816(acc[0][2*p + 1], ah0, bh[2], bh[3]);
                MMA16816(acc[1][2*p],     ah1, bh[0], bh[1]);
                MMA16816(acc[1][2*p + 1], ah1, bh[2], bh[3]);
                MMA16816(acc[0][2*p],     ah0, bl[0], bl[1]);
                MMA16816(acc[0][2*p + 1], ah0, bl[2], bl[3]);
                MMA16816(acc[1][2*p],     ah1, bl[0], bl[1]);
                MMA16816(acc[1][2*p + 1], ah1, bl[2], bl[3]);
                MMA16816(acc[0][2*p],     al0, bh[0], bh[1]);
                MMA16816(acc[0][2*p + 1], al0, bh[2], bh[3]);
                MMA16816(acc[1][2*p],     al1, bh[0], bh[1]);
                MMA16816(acc[1][2*p + 1], al1, bh[2], bh[3]);
            }
        }

        // ---- epilogue: tanh.approx + LN (warp-local stats) + weighting ----
        {
            float acoef[2][2], bsum = 0.f, ws = 0.f;
            #pragma unroll
            for (int f = 0; f < 2; ++f) {
                float s1a = 0.f, s2a = 0.f, s1b = 0.f, s2b = 0.f;
                #pragma unroll
                for (int nt = 0; nt < 16; ++nt) {
                    int c0 = nt * 8 + qc * 2;
                    float x0 = tanha(acc[f][nt][0] + bv2s[c0]);
                    float x1 = tanha(acc[f][nt][1] + bv2s[c0 + 1]);
                    float x2 = tanha(acc[f][nt][2] + bv2s[c0]);
                    float x3 = tanha(acc[f][nt][3] + bv2s[c0 + 1]);
                    acc[f][nt][0] = x0; acc[f][nt][1] = x1;
                    acc[f][nt][2] = x2; acc[f][nt][3] = x3;
                    s1a += x0 + x1; s2a += x0 * x0 + x1 * x1;
                    s1b += x2 + x3; s2b += x2 * x2 + x3 * x3;
                }
                #pragma unroll
                for (int off = 1; off <= 2; off <<= 1) {
                    s1a += __shfl_xor_sync(0xffffffffu, s1a, off);
                    s2a += __shfl_xor_sync(0xffffffffu, s2a, off);
                    s1b += __shfl_xor_sync(0xffffffffu, s1b, off);
                    s2b += __shfl_xor_sync(0xffffffffu, s2b, off);
                }
                float mua = s1a * (1.f / 128.f);
                float rsa = rsqrtf(s2a * (1.f / 128.f) - mua * mua + 1e-5f);
                float mub = s1b * (1.f / 128.f);
                float rsb = rsqrtf(s2b * (1.f / 128.f) - mub * mub + 1e-5f);
                // global tile row = w*32 + f*16 + qr (+8); arow idx = (w>>1)*64 + (row & 63)
                int ri = (w >> 1) * 64 + (((w & 1) * 32 + f * 16 + qr) & 63);
                float wa = arow[ri], wb = arow[ri + 8];
                acoef[f][0] = wa * rsa;
                acoef[f][1] = wb * rsb;
                bsum += wa * rsa * mua + wb * rsb * mub;
                ws += wa + wb;
            }

            float part[32];
            #pragma unroll
            for (int nt = 0; nt < 16; ++nt) {
                #pragma unroll
                for (int jj = 0; jj < 2; ++jj) {
                    int c = nt * 8 + qc * 2 + jj;
                    float inner = acoef[0][0] * acc[0][nt][jj]
                                + acoef[0][1] * acc[0][nt][jj + 2]
                                + acoef[1][0] * acc[1][nt][jj]
                                + acoef[1][1] * acc[1][nt][jj + 2]
                                - bsum;
                    part[nt * 2 + jj] = gvs[c] * inner + bevs[c] * ws;
                }
            }
            #pragma unroll
            for (int off = 4; off <= 16; off <<= 1)
                #pragma unroll
                for (int s = 0; s < 32; ++s)
                    part[s] += __shfl_xor_sync(0xffffffffu, part[s], off);
            if (l < 4) {
                #pragma unroll
                for (int nt = 0; nt < 16; ++nt) {
                    red[w * 128 + nt * 8 + l * 2 + 0] = part[nt * 2 + 0];
                    red[w * 128 + nt * 8 + l * 2 + 1] = part[nt * 2 + 1];
                }
            }
        }
        __syncthreads();

        // ---- final: combine the two warps of each n, store g_G ----
        {
            #pragma unroll
            for (int q = 0; q < 2; ++q) {
                int o = t + q * 256;
                int nl = o >> 7, c = o & 127;
                g_G[(bc * 64 + n0 + nl) * 128 + c] =
                    red[(nl * 2) * 128 + c] + red[(nl * 2 + 1) * 128 + c];
            }
        }
        __syncthreads();
    }
}

// =====================================================================
// Kernel C: out = g @ Wv3 + asum * bv3. grid (64, 2) column halves
// =====================================================================
__global__ __launch_bounds__(256) void kC(Params P, float* __restrict__ out) {
    extern __shared__ float sm[];
    float* A = sm;          // 8192
    float* W = sm + 8192;   // 8192 (128 x 64 half)
    const int t = threadIdx.x, tx = t & 15, ty = t >> 4;
    const int bc = blockIdx.x, half = blockIdx.y;
    const int r0 = ty * 4;

    cp4(A, g_G + bc * 8192, 8192, t);
    {
        const float* Wv3 = P.p[16];
        for (int i = t; i < 8192; i += NTHREADS) {
            int k = i >> 6, c = i & 63;
            W[i] = Wv3[k * 128 + half * 64 + c];
        }
    }
    __syncthreads();

    float acc[4][4];
    #pragma unroll
    for (int i = 0; i < 4; ++i)
        #pragma unroll
        for (int j = 0; j < 4; ++j) acc[i][j] = 0.f;
    #pragma unroll 4
    for (int k = 0; k < 128; ++k) {
        float a[4];
        #pragma unroll
        for (int i = 0; i < 4; ++i) a[i] = A[(r0 + i) * 128 + k];
        float4 b4 = *reinterpret_cast<const float4*>(W + k * 64 + tx * 4);
        float bb[4] = {b4.x, b4.y, b4.z, b4.w};
        #pragma unroll
        for (int i = 0; i < 4; ++i)
            #pragma unroll
            for (int j = 0; j < 4; ++j)
                acc[i][j] = fmaf(a[i], bb[j], acc[i][j]);
    }

    const float* bv3 = P.p[17];
    #pragma unroll
    for (int i = 0; i < 4; ++i) {
        int r = r0 + i;
        float as = g_asum[bc * 64 + r];
        float4 v;
        int cb = half * 64 + tx * 4;
        v.x = acc[i][0] + as * bv3[cb + 0];
        v.y = acc[i][1] + as * bv3[cb + 1];
        v.z = acc[i][2] + as * bv3[cb + 2];
        v.w = acc[i][3] + as * bv3[cb + 3];
        *reinterpret_cast<float4*>(out + (bc * 64 + r) * 128 + cb) = v;
    }
}

// =====================================================================
extern "C" void kernel_launch(void* const* d_in, const int* in_sizes, int n_in,
                              void* d_out, int out_size) {
    (void)in_sizes; (void)n_in; (void)out_size;
    Params P;
    for (int i = 0; i < 24; ++i) P.p[i] = reinterpret_cast<const float*>(d_in[i]);

    const int SMEM_A1 = (6144 + 16384 + 8192 + 8192) * 4;
    const int SMEM_A2 = (8256 + 8256 + 64 * 65) * 4;
    const int SMEM_B  = KB_SMEM_BYTES;
    const int SMEM_C  = (8192 + 8192) * 4;

    cudaFuncSetAttribute(kA1, cudaFuncAttributeMaxDynamicSharedMemorySize, SMEM_A1);
    cudaFuncSetAttribute(kA2, cudaFuncAttributeMaxDynamicSharedMemorySize, SMEM_A2);
    cudaFuncSetAttribute(kB,  cudaFuncAttributeMaxDynamicSharedMemorySize, SMEM_B);
    cudaFuncSetAttribute(kC,  cudaFuncAttributeMaxDynamicSharedMemorySize, SMEM_C);

    kW <<<64, 256>>>(P);
    kA1<<<dim3(64, 2), NTHREADS, SMEM_A1>>>(P);
    kA2<<<64, NTHREADS, SMEM_A2>>>(P);
    kB <<<148, 256, SMEM_B>>>(P);
    kC <<<dim3(64, 2), NTHREADS, SMEM_C>>>(P, reinterpret_cast<float*>(d_out));
}

// round 9
// speedup vs baseline: 1.0495x; 1.0495x over previous
#include <cuda_runtime.h>
#include <cuda_bf16.h>
#include <cuda_fp16.h>

#define NTHREADS 256

struct Params { const float* p[24]; };

// ---- scratch (static device globals; no allocation) ----
__device__ float g_keys   [64*64*128];
__device__ float g_queries[64*64*128];
__device__ float g_hk     [64*64*128];
__device__ float g_hq     [64*64*128];
__device__ float g_attn   [64*64*64];
__device__ float g_asum   [64*64];
__device__ float g_G      [64*64*128];
// Wv2^T as [n=s_out][k=s_in], fp16, rows padded to 136 elems (272B)
__device__ __align__(16) unsigned short g_Wh[128*136];

__device__ __forceinline__ float tanha(float x) {
    float y;
    asm("tanh.approx.f32 %0, %1;" : "=f"(y) : "f"(x));
    return y;
}

__device__ __forceinline__ void cp4(float* dst, const float* src, int n, int t) {
    for (int i = t*4; i < n; i += NTHREADS*4)
        *reinterpret_cast<float4*>(dst + i) = *reinterpret_cast<const float4*>(src + i);
}

__device__ __forceinline__ int colidx(int tx, int j) { return j < 4 ? tx*4 + j : 60 + tx*4 + j; }

__device__ __forceinline__ void zero_acc8(float acc[4][8]) {
    #pragma unroll
    for (int i = 0; i < 4; ++i)
        #pragma unroll
        for (int j = 0; j < 8; ++j) acc[i][j] = 0.f;
}

template<int K>
__device__ __forceinline__ void gemm_tile(const float* __restrict__ A, const float* __restrict__ W,
                                          float acc[4][8], int tx, int ty) {
    const int r0 = ty * 4;
    const int ca = tx * 4, cb = 64 + tx * 4;
    #pragma unroll 4
    for (int k = 0; k < K; ++k) {
        float aa[4];
        #pragma unroll
        for (int i = 0; i < 4; ++i) aa[i] = A[(r0 + i) * K + k];
        float4 b0 = *reinterpret_cast<const float4*>(W + k * 128 + ca);
        float4 b1 = *reinterpret_cast<const float4*>(W + k * 128 + cb);
        float bb[8] = {b0.x, b0.y, b0.z, b0.w, b1.x, b1.y, b1.z, b1.w};
        #pragma unroll
        for (int i = 0; i < 4; ++i)
            #pragma unroll
            for (int j = 0; j < 8; ++j)
                acc[i][j] = fmaf(aa[i], bb[j], acc[i][j]);
    }
}

__device__ __forceinline__ void store_row4(float* base, int row, int tx, const float v[8]) {
    *reinterpret_cast<float4*>(base + row * 128 + tx * 4)      = make_float4(v[0], v[1], v[2], v[3]);
    *reinterpret_cast<float4*>(base + row * 128 + 64 + tx * 4) = make_float4(v[4], v[5], v[6], v[7]);
}

__device__ __forceinline__ unsigned smem_u32(const void* p) {
    unsigned a;
    asm("{ .reg .u64 t; cvta.to.shared.u64 t, %1; cvt.u32.u64 %0, t; }" : "=r"(a) : "l"(p));
    return a;
}

#define LDSM_X4(r, addr)                                                       \
    asm volatile("ldmatrix.sync.aligned.m8n8.x4.shared.b16 {%0,%1,%2,%3}, [%4];" \
        : "=r"((r)[0]), "=r"((r)[1]), "=r"((r)[2]), "=r"((r)[3]) : "r"(addr))

#define MMA16816(d, a, b0, b1)                                                 \
    asm volatile("mma.sync.aligned.m16n8k16.row.col.f32.f16.f16.f32 "          \
        "{%0,%1,%2,%3}, {%4,%5,%6,%7}, {%8,%9}, {%0,%1,%2,%3};"                \
        : "+f"((d)[0]), "+f"((d)[1]), "+f"((d)[2]), "+f"((d)[3])               \
        : "r"((a)[0]), "r"((a)[1]), "r"((a)[2]), "r"((a)[3]), "r"(b0), "r"(b1))

#define GBAR(gid)                                                              \
    asm volatile("bar.sync %0, %1;" :: "r"(gid), "r"(256u) : "memory")

// =====================================================================
// Kernel kW: precompute Wv2^T fp16 into padded [128][136]. grid 64
// =====================================================================
__global__ __launch_bounds__(256) void kW(Params P) {
    int t = blockIdx.x * 256 + threadIdx.x;
    const float* Wv2 = P.p[14];
    if (t < 16384) {
        int n = t >> 7, k = t & 127;
        g_Wh[n * 136 + k] = __half_as_ushort(__float2half_rn(Wv2[k * 128 + n]));
    }
}

// =====================================================================
// Kernel A1: keys / queries MLPs + hk, hq projections. grid (64 bc, 2 paths)
// =====================================================================
__global__ __launch_bounds__(256) void kA1(Params P) {
    extern __shared__ float sm[];
    float* X  = sm;
    float* W  = sm + 6144;
    float* T1 = W + 16384;
    float* T2 = T1 + 8192;
    const int t = threadIdx.x, tx = t & 15, ty = t >> 4;
    const int bc = blockIdx.x;
    const int r0 = ty * 4;
    float acc[4][8];

    if (blockIdx.y == 0) {
        cp4(X, P.p[0] + bc * 6144, 6144, t);
        cp4(W, P.p[2], 12288, t);
        __syncthreads();
        zero_acc8(acc);
        gemm_tile<96>(X, W, acc, tx, ty);
        {
            const float aK = P.p[18][0];
            const float* bk1 = P.p[3];
            #pragma unroll
            for (int i = 0; i < 4; ++i) {
                float v[8];
                #pragma unroll
                for (int j = 0; j < 8; ++j) {
                    int c = colidx(tx, j);
                    float x = acc[i][j] + bk1[c];
                    v[j] = x >= 0.f ? x : aK * x;
                }
                store_row4(T1, r0 + i, tx, v);
            }
        }
        __syncthreads();
        cp4(W, P.p[4], 16384, t);
        __syncthreads();
        zero_acc8(acc);
        gemm_tile<128>(T1, W, acc, tx, ty);
        {
            const float* bk2 = P.p[5];
            const float* gK  = P.p[20];
            const float* beK = P.p[21];
            #pragma unroll
            for (int i = 0; i < 4; ++i) {
                float v[8]; float s1 = 0.f, s2 = 0.f;
                #pragma unroll
                for (int j = 0; j < 8; ++j) {
                    int c = colidx(tx, j);
                    float x = tanha(acc[i][j] + bk2[c]);
                    v[j] = x; s1 += x; s2 += x * x;
                }
                #pragma unroll
                for (int off = 8; off >= 1; off >>= 1) {
                    s1 += __shfl_xor_sync(0xffffffffu, s1, off);
                    s2 += __shfl_xor_sync(0xffffffffu, s2, off);
                }
                float m  = s1 * (1.f / 128.f);
                float va = s2 * (1.f / 128.f) - m * m;
                float rs = rsqrtf(va + 1e-5f);
                #pragma unroll
                for (int j = 0; j < 8; ++j) {
                    int c = colidx(tx, j);
                    v[j] = (v[j] - m) * rs * gK[c] + beK[c];
                }
                store_row4(T2, r0 + i, tx, v);
            }
        }
        __syncthreads();
        cp4(W, P.p[6], 16384, t);
        __syncthreads();
        zero_acc8(acc);
        gemm_tile<128>(T2, W, acc, tx, ty);
        {
            const float* bk3 = P.p[7];
            float* kout = g_keys + bc * 8192;
            #pragma unroll
            for (int i = 0; i < 4; ++i) {
                float v[8];
                #pragma unroll
                for (int j = 0; j < 8; ++j) v[j] = acc[i][j] + bk3[colidx(tx, j)];
                store_row4(T1, r0 + i, tx, v);
                store_row4(kout, r0 + i, tx, v);
            }
        }
        __syncthreads();
        cp4(W, P.p[12] + 16384, 16384, t);
        __syncthreads();
        zero_acc8(acc);
        gemm_tile<128>(T1, W, acc, tx, ty);
        {
            float* hkout = g_hk + bc * 8192;
            #pragma unroll
            for (int i = 0; i < 4; ++i) {
                float v[8];
                #pragma unroll
                for (int j = 0; j < 8; ++j) v[j] = acc[i][j];
                store_row4(hkout, r0 + i, tx, v);
            }
        }
    } else {
        cp4(X, P.p[1] + bc * 6144, 6144, t);
        cp4(W, P.p[8], 12288, t);
        __syncthreads();
        zero_acc8(acc);
        gemm_tile<96>(X, W, acc, tx, ty);
        {
            const float* bq1 = P.p[9];
            #pragma unroll
            for (int i = 0; i < 4; ++i) {
                float v[8];
                #pragma unroll
                for (int j = 0; j < 8; ++j) v[j] = tanha(acc[i][j] + bq1[colidx(tx, j)]);
                store_row4(T1, r0 + i, tx, v);
            }
        }
        __syncthreads();
        cp4(W, P.p[10], 16384, t);
        __syncthreads();
        zero_acc8(acc);
        gemm_tile<128>(T1, W, acc, tx, ty);
        {
            const float* bq2 = P.p[11];
            float* qout = g_queries + bc * 8192;
            #pragma unroll
            for (int i = 0; i < 4; ++i) {
                float v[8];
                #pragma unroll
                for (int j = 0; j < 8; ++j) v[j] = acc[i][j] + bq2[colidx(tx, j)];
                store_row4(T2, r0 + i, tx, v);
                store_row4(qout, r0 + i, tx, v);
            }
        }
        __syncthreads();
        cp4(W, P.p[12], 16384, t);
        __syncthreads();
        zero_acc8(acc);
        gemm_tile<128>(T2, W, acc, tx, ty);
        {
            float* hqout = g_hq + bc * 8192;
            #pragma unroll
            for (int i = 0; i < 4; ++i) {
                float v[8];
                #pragma unroll
                for (int j = 0; j < 8; ++j) v[j] = acc[i][j];
                store_row4(hqout, r0 + i, tx, v);
            }
        }
    }
}

// =====================================================================
// Kernel A2: logits + softmax over n (axis 2) + attn row sums. grid 64
// =====================================================================
__global__ __launch_bounds__(256) void kA2(Params P) {
    extern __shared__ float sm[];
    float* Kp = sm;
    float* Q  = sm + 8256;
    float* L  = Q + 8256;
    const int t = threadIdx.x, tx = t & 15, ty = t >> 4;
    const int bc = blockIdx.x;

    for (int i = t; i < 8192; i += NTHREADS) {
        int r = i >> 7, c = i & 127;
        Kp[r * 129 + c] = g_keys[bc * 8192 + i];
        Q [r * 129 + c] = g_queries[bc * 8192 + i];
    }
    __syncthreads();

    float acc[4][4];
    #pragma unroll
    for (int i = 0; i < 4; ++i)
        #pragma unroll
        for (int j = 0; j < 4; ++j) acc[i][j] = 0.f;
    #pragma unroll 4
    for (int k = 0; k < 128; ++k) {
        float a[4], b[4];
        #pragma unroll
        for (int i = 0; i < 4; ++i) a[i] = Kp[(ty * 4 + i) * 129 + k];
        #pragma unroll
        for (int j = 0; j < 4; ++j) b[j] = Q[(tx * 4 + j) * 129 + k];
        #pragma unroll
        for (int i = 0; i < 4; ++i)
            #pragma unroll
            for (int j = 0; j < 4; ++j) acc[i][j] = fmaf(a[i], b[j], acc[i][j]);
    }
    #pragma unroll
    for (int i = 0; i < 4; ++i)
        #pragma unroll
        for (int j = 0; j < 4; ++j) L[(ty * 4 + i) * 65 + tx * 4 + j] = acc[i][j];
    __syncthreads();

    if (t < 64) {
        int m = t;
        float mx = -1e30f;
        for (int n = 0; n < 64; ++n) mx = fmaxf(mx, L[n * 65 + m]);
        float s = 0.f;
        for (int n = 0; n < 64; ++n) { float e = expf(L[n * 65 + m] - mx); L[n * 65 + m] = e; s += e; }
        float inv = 1.f / s;
        for (int n = 0; n < 64; ++n) L[n * 65 + m] *= inv;
    }
    __syncthreads();
    if (t < 64) {
        int n = t; float s = 0.f;
        for (int m = 0; m < 64; ++m) {
            float v = L[n * 65 + m];
            g_attn[bc * 4096 + n * 64 + m] = v;
            s += v;
        }
        g_asum[bc * 64 + n] = s;
    }
}

// =====================================================================
// Kernel B (persistent, dual-group HMMA, fp16 2-chain): grid 148 x 512.
// Two 8-warp groups share W fp16 (loaded once); each group 16x128 tiles.
// A = prelu(hq+hk+bv1) split fp16 hi/lo; D = (Ah+Al)@Wh (2 chains).
// =====================================================================
// byte offsets within dynamic smem
#define KB_WHI    0u               // 34816 B (fp16 W)
#define KB_A      34816u           // + group*69632: Ahi; Alo = +34816
#define KB_CONST  174080u          // bv1s, bv2s, gvs, bevs (128 floats each)
#define KB_GRP    176128u          // + group*5632: arow(512B) hkn(1024B) red(4096B)
#define KB_SMEM_BYTES 187392

__global__ __launch_bounds__(512, 1) void kB(Params P) {
    extern __shared__ char smc[];
    const int t = threadIdx.x;
    const int wid = t >> 5, l = t & 31;
    const int group = wid >> 3;         // 0 or 1
    const int gt = t & 255;             // thread within group
    const int gw = wid & 7;             // warp within group
    const int gid = group + 1;          // named barrier id

    float* bv1s = reinterpret_cast<float*>(smc + KB_CONST);
    float* bv2s = bv1s + 128;
    float* gvs  = bv2s + 128;
    float* bevs = gvs + 128;
    char* grp  = smc + KB_GRP + group * 5632u;
    float* arow = reinterpret_cast<float*>(grp);
    float* hkn  = arow + 128;
    float* red  = hkn + 256;            // 8 warps x 128

    unsigned short* Ahi = reinterpret_cast<unsigned short*>(smc + KB_A + group * 69632u);
    unsigned short* Alo = reinterpret_cast<unsigned short*>(reinterpret_cast<char*>(Ahi) + 34816);

    // ---- one-time staging: W fp16 + const vectors (all 512 threads) ----
    {
        const float4* s0 = reinterpret_cast<const float4*>(g_Wh);
        float4* d0 = reinterpret_cast<float4*>(smc + KB_WHI);
        for (int i = t; i < 2176; i += 512) d0[i] = s0[i];
        if (t < 128) {
            bv1s[t] = P.p[13][t];
            bv2s[t] = P.p[15][t];
            gvs[t]  = P.p[22][t];
            bevs[t] = P.p[23][t];
        }
    }
    __syncthreads();

    const float aV = P.p[19][0];
    const unsigned sbase = smem_u32(smc);
    const unsigned aHiAddr = sbase + KB_A + group * 69632u
                           + ((gw * 16 + (l & 15)) * 136) * 2 + (l >> 4) * 16;
    const unsigned aLoAddr = aHiAddr + 34816;
    const unsigned bRow = (l & 7) + ((l >> 4) & 1) * 8;
    const unsigned bAddr = sbase + KB_WHI + (bRow * 136) * 2 + ((l >> 3) & 1) * 16;

    for (int item = blockIdx.x * 2 + group; item < 2048; item += 296) {
        const int bc = item >> 5;
        const int n0 = (item & 31) * 2;

        // ---- per-item staging ----
        if (gt < 128) arow[gt] = g_attn[bc * 4096 + n0 * 64 + gt];
        hkn[gt] = g_hk[(bc * 64 + n0) * 128 + gt];
        GBAR(gid);

        // ---- build A tile (rows = n_l*64+m, cols = k), fp16 hi/lo ----
        {
            const int r = gt >> 1, ac = gt & 1;
            const int m = r & 63, nl = r >> 6;
            const float* hq = g_hq + bc * 8192 + m * 128 + ac * 64;
            const float* hk = hkn + nl * 128 + ac * 64;
            const float* bv = bv1s + ac * 64;
            unsigned short* ph = Ahi + r * 136 + ac * 64;
            unsigned short* pl = Alo + r * 136 + ac * 64;
            #pragma unroll 4
            for (int j = 0; j < 16; ++j) {
                float4 h  = *reinterpret_cast<const float4*>(hq + j * 4);
                float4 kk = *reinterpret_cast<const float4*>(hk + j * 4);
                float4 bb = *reinterpret_cast<const float4*>(bv + j * 4);
                float a0 = h.x + kk.x + bb.x; a0 = a0 >= 0.f ? a0 : aV * a0;
                float a1 = h.y + kk.y + bb.y; a1 = a1 >= 0.f ? a1 : aV * a1;
                float a2 = h.z + kk.z + bb.z; a2 = a2 >= 0.f ? a2 : aV * a2;
                float a3 = h.w + kk.w + bb.w; a3 = a3 >= 0.f ? a3 : aV * a3;
                __half h0 = __float2half_rn(a0), h1 = __float2half_rn(a1);
                __half h2 = __float2half_rn(a2), h3 = __float2half_rn(a3);
                __half l0 = __float2half_rn(a0 - __half2float(h0));
                __half l1 = __float2half_rn(a1 - __half2float(h1));
                __half l2 = __float2half_rn(a2 - __half2float(h2));
                __half l3 = __float2half_rn(a3 - __half2float(h3));
                uint2 vh, vl;
                vh.x = (unsigned)__half_as_ushort(h0) | ((unsigned)__half_as_ushort(h1) << 16);
                vh.y = (unsigned)__half_as_ushort(h2) | ((unsigned)__half_as_ushort(h3) << 16);
                vl.x = (unsigned)__half_as_ushort(l0) | ((unsigned)__half_as_ushort(l1) << 16);
                vl.y = (unsigned)__half_as_ushort(l2) | ((unsigned)__half_as_ushort(l3) << 16);
                *reinterpret_cast<uint2*>(ph + j * 4) = vh;
                *reinterpret_cast<uint2*>(pl + j * 4) = vl;
            }
        }
        GBAR(gid);

        // ---- GEMM: 8 warps x (16m x 128n), K=128, 2 chains (Ah+Al)@Wh ----
        float acc[16][4];
        #pragma unroll
        for (int nt = 0; nt < 16; ++nt)
            #pragma unroll
            for (int j = 0; j < 4; ++j) acc[nt][j] = 0.f;

        #pragma unroll
        for (int ks = 0; ks < 8; ++ks) {
            unsigned ah[4], al[4];
            LDSM_X4(ah, aHiAddr + ks * 32);
            LDSM_X4(al, aLoAddr + ks * 32);
            #pragma unroll
            for (int p = 0; p < 8; ++p) {
                unsigned bh[4];
                LDSM_X4(bh, bAddr + p * 4352 + ks * 32);
                MMA16816(acc[2*p],     ah, bh[0], bh[1]);
                MMA16816(acc[2*p + 1], ah, bh[2], bh[3]);
                MMA16816(acc[2*p],     al, bh[0], bh[1]);
                MMA16816(acc[2*p + 1], al, bh[2], bh[3]);
            }
        }

        // ---- epilogue: tanh.approx + LN + attn-weighted reduce over m ----
        {
            const int qr = l >> 2, qc = l & 3;
            const int r0 = gw * 16 + qr, r1 = r0 + 8;
            float s1a = 0.f, s2a = 0.f, s1b = 0.f, s2b = 0.f;
            #pragma unroll
            for (int nt = 0; nt < 16; ++nt) {
                int c0 = nt * 8 + qc * 2;
                float x0 = tanha(acc[nt][0] + bv2s[c0]);
                float x1 = tanha(acc[nt][1] + bv2s[c0 + 1]);
                float x2 = tanha(acc[nt][2] + bv2s[c0]);
                float x3 = tanha(acc[nt][3] + bv2s[c0 + 1]);
                acc[nt][0] = x0; acc[nt][1] = x1; acc[nt][2] = x2; acc[nt][3] = x3;
                s1a += x0 + x1; s2a += x0 * x0 + x1 * x1;
                s1b += x2 + x3; s2b += x2 * x2 + x3 * x3;
            }
            #pragma unroll
            for (int off = 1; off <= 2; off <<= 1) {
                s1a += __shfl_xor_sync(0xffffffffu, s1a, off);
                s2a += __shfl_xor_sync(0xffffffffu, s2a, off);
                s1b += __shfl_xor_sync(0xffffffffu, s1b, off);
                s2b += __shfl_xor_sync(0xffffffffu, s2b, off);
            }
            float mua = s1a * (1.f / 128.f);
            float rsa = rsqrtf(s2a * (1.f / 128.f) - mua * mua + 1e-5f);
            float mub = s1b * (1.f / 128.f);
            float rsb = rsqrtf(s2b * (1.f / 128.f) - mub * mub + 1e-5f);
            float wa = arow[r0], wb = arow[r1];

            float part[32];
            #pragma unroll
            for (int nt = 0; nt < 16; ++nt) {
                #pragma unroll
                for (int jj = 0; jj < 2; ++jj) {
                    int c = nt * 8 + qc * 2 + jj;
                    float oa = (acc[nt][jj]     - mua) * rsa * gvs[c] + bevs[c];
                    float ob = (acc[nt][jj + 2] - mub) * rsb * gvs[c] + bevs[c];
                    part[nt * 2 + jj] = wa * oa + wb * ob;
                }
            }
            #pragma unroll
            for (int off = 4; off <= 16; off <<= 1)
                #pragma unroll
                for (int s = 0; s < 32; ++s)
                    part[s] += __shfl_xor_sync(0xffffffffu, part[s], off);
            if (l < 4) {
                #pragma unroll
                for (int nt = 0; nt < 16; ++nt) {
                    red[gw * 128 + nt * 8 + l * 2 + 0] = part[nt * 2 + 0];
                    red[gw * 128 + nt * 8 + l * 2 + 1] = part[nt * 2 + 1];
                }
            }
        }
        GBAR(gid);

        {
            const int nl = gt >> 7, c = gt & 127;
            const float* rb = red + nl * 512 + c;
            g_G[(bc * 64 + n0 + nl) * 128 + c] = rb[0] + rb[128] + rb[256] + rb[384];
        }
        GBAR(gid);
    }
}

// =====================================================================
// Kernel C: out = g @ Wv3 + asum * bv3. grid (64, 2) column halves
// =====================================================================
__global__ __launch_bounds__(256) void kC(Params P, float* __restrict__ out) {
    extern __shared__ float sm[];
    float* A = sm;          // 8192
    float* W = sm + 8192;   // 8192 (128 x 64 half)
    const int t = threadIdx.x, tx = t & 15, ty = t >> 4;
    const int bc = blockIdx.x, half = blockIdx.y;
    const int r0 = ty * 4;

    cp4(A, g_G + bc * 8192, 8192, t);
    {
        const float* Wv3 = P.p[16];
        for (int i = t; i < 8192; i += NTHREADS) {
            int k = i >> 6, c = i & 63;
            W[i] = Wv3[k * 128 + half * 64 + c];
        }
    }
    __syncthreads();

    float acc[4][4];
    #pragma unroll
    for (int i = 0; i < 4; ++i)
        #pragma unroll
        for (int j = 0; j < 4; ++j) acc[i][j] = 0.f;
    #pragma unroll 4
    for (int k = 0; k < 128; ++k) {
        float a[4];
        #pragma unroll
        for (int i = 0; i < 4; ++i) a[i] = A[(r0 + i) * 128 + k];
        float4 b4 = *reinterpret_cast<const float4*>(W + k * 64 + tx * 4);
        float bb[4] = {b4.x, b4.y, b4.z, b4.w};
        #pragma unroll
        for (int i = 0; i < 4; ++i)
            #pragma unroll
            for (int j = 0; j < 4; ++j)
                acc[i][j] = fmaf(a[i], bb[j], acc[i][j]);
    }

    const float* bv3 = P.p[17];
    #pragma unroll
    for (int i = 0; i < 4; ++i) {
        int r = r0 + i;
        float as = g_asum[bc * 64 + r];
        float4 v;
        int cb = half * 64 + tx * 4;
        v.x = acc[i][0] + as * bv3[cb + 0];
        v.y = acc[i][1] + as * bv3[cb + 1];
        v.z = acc[i][2] + as * bv3[cb + 2];
        v.w = acc[i][3] + as * bv3[cb + 3];
        *reinterpret_cast<float4*>(out + (bc * 64 + r) * 128 + cb) = v;
    }
}

// =====================================================================
extern "C" void kernel_launch(void* const* d_in, const int* in_sizes, int n_in,
                              void* d_out, int out_size) {
    (void)in_sizes; (void)n_in; (void)out_size;
    Params P;
    for (int i = 0; i < 24; ++i) P.p[i] = reinterpret_cast<const float*>(d_in[i]);

    const int SMEM_A1 = (6144 + 16384 + 8192 + 8192) * 4;
    const int SMEM_A2 = (8256 + 8256 + 64 * 65) * 4;
    const int SMEM_B  = KB_SMEM_BYTES;
    const int SMEM_C  = (8192 + 8192) * 4;

    cudaFuncSetAttribute(kA1, cudaFuncAttributeMaxDynamicSharedMemorySize, SMEM_A1);
    cudaFuncSetAttribute(kA2, cudaFuncAttributeMaxDynamicSharedMemorySize, SMEM_A2);
    cudaFuncSetAttribute(kB,  cudaFuncAttributeMaxDynamicSharedMemorySize, SMEM_B);
    cudaFuncSetAttribute(kC,  cudaFuncAttributeMaxDynamicSharedMemorySize, SMEM_C);

    kW <<<64, 256>>>(P);
    kA1<<<dim3(64, 2), NTHREADS, SMEM_A1>>>(P);
    kA2<<<64, NTHREADS, SMEM_A2>>>(P);
    kB <<<148, 512, SMEM_B>>>(P);
    kC <<<dim3(64, 2), NTHREADS, SMEM_C>>>(P, reinterpret_cast<float*>(d_out));
}

// round 10
// speedup vs baseline: 1.0587x; 1.0087x over previous
#include <cuda_runtime.h>
#include <cuda_bf16.h>
#include <cuda_fp16.h>

#define NTHREADS 256

struct Params { const float* p[24]; };

// ---- scratch (static device globals; no allocation) ----
__device__ float g_keys   [64*64*128];
__device__ float g_queries[64*64*128];
__device__ float g_hk     [64*64*128];
__device__ float g_hq     [64*64*128];
__device__ float g_attn   [64*64*64];
__device__ float g_asum   [64*64];
__device__ float g_G      [64*64*128];
// Wv2^T as [n=s_out][k=s_in], fp16, rows padded to 136 elems (272B)
__device__ __align__(16) unsigned short g_Wh[128*136];

__device__ __forceinline__ float tanha(float x) {
    float y;
    asm("tanh.approx.f32 %0, %1;" : "=f"(y) : "f"(x));
    return y;
}

__device__ __forceinline__ void cp4(float* dst, const float* src, int n, int t) {
    for (int i = t*4; i < n; i += NTHREADS*4)
        *reinterpret_cast<float4*>(dst + i) = *reinterpret_cast<const float4*>(src + i);
}

__device__ __forceinline__ int colidx(int tx, int j) { return j < 4 ? tx*4 + j : 60 + tx*4 + j; }

__device__ __forceinline__ void zero_acc8(float acc[4][8]) {
    #pragma unroll
    for (int i = 0; i < 4; ++i)
        #pragma unroll
        for (int j = 0; j < 8; ++j) acc[i][j] = 0.f;
}

template<int K>
__device__ __forceinline__ void gemm_tile(const float* __restrict__ A, const float* __restrict__ W,
                                          float acc[4][8], int tx, int ty) {
    const int r0 = ty * 4;
    const int ca = tx * 4, cb = 64 + tx * 4;
    #pragma unroll 4
    for (int k = 0; k < K; ++k) {
        float aa[4];
        #pragma unroll
        for (int i = 0; i < 4; ++i) aa[i] = A[(r0 + i) * K + k];
        float4 b0 = *reinterpret_cast<const float4*>(W + k * 128 + ca);
        float4 b1 = *reinterpret_cast<const float4*>(W + k * 128 + cb);
        float bb[8] = {b0.x, b0.y, b0.z, b0.w, b1.x, b1.y, b1.z, b1.w};
        #pragma unroll
        for (int i = 0; i < 4; ++i)
            #pragma unroll
            for (int j = 0; j < 8; ++j)
                acc[i][j] = fmaf(aa[i], bb[j], acc[i][j]);
    }
}

__device__ __forceinline__ void store_row4(float* base, int row, int tx, const float v[8]) {
    *reinterpret_cast<float4*>(base + row * 128 + tx * 4)      = make_float4(v[0], v[1], v[2], v[3]);
    *reinterpret_cast<float4*>(base + row * 128 + 64 + tx * 4) = make_float4(v[4], v[5], v[6], v[7]);
}

__device__ __forceinline__ unsigned smem_u32(const void* p) {
    unsigned a;
    asm("{ .reg .u64 t; cvta.to.shared.u64 t, %1; cvt.u32.u64 %0, t; }" : "=r"(a) : "l"(p));
    return a;
}

#define LDSM_X4(r, addr)                                                       \
    asm volatile("ldmatrix.sync.aligned.m8n8.x4.shared.b16 {%0,%1,%2,%3}, [%4];" \
        : "=r"((r)[0]), "=r"((r)[1]), "=r"((r)[2]), "=r"((r)[3]) : "r"(addr))

#define MMA16816(d, a, b0, b1)                                                 \
    asm volatile("mma.sync.aligned.m16n8k16.row.col.f32.f16.f16.f32 "          \
        "{%0,%1,%2,%3}, {%4,%5,%6,%7}, {%8,%9}, {%0,%1,%2,%3};"                \
        : "+f"((d)[0]), "+f"((d)[1]), "+f"((d)[2]), "+f"((d)[3])               \
        : "r"((a)[0]), "r"((a)[1]), "r"((a)[2]), "r"((a)[3]), "r"(b0), "r"(b1))

#define GBAR(gid)                                                              \
    asm volatile("bar.sync %0, %1;" :: "r"(gid), "r"(256u) : "memory")

// =====================================================================
// Kernel kW: precompute Wv2^T fp16 into padded [128][136]. grid 64
// =====================================================================
__global__ __launch_bounds__(256) void kW(Params P) {
    int t = blockIdx.x * 256 + threadIdx.x;
    const float* Wv2 = P.p[14];
    if (t < 16384) {
        int n = t >> 7, k = t & 127;
        g_Wh[n * 136 + k] = __half_as_ushort(__float2half_rn(Wv2[k * 128 + n]));
    }
}

// =====================================================================
// Kernel A1: keys / queries MLPs + hk, hq projections. grid (64 bc, 2 paths)
// =====================================================================
__global__ __launch_bounds__(256) void kA1(Params P) {
    extern __shared__ float sm[];
    float* X  = sm;
    float* W  = sm + 6144;
    float* T1 = W + 16384;
    float* T2 = T1 + 8192;
    const int t = threadIdx.x, tx = t & 15, ty = t >> 4;
    const int bc = blockIdx.x;
    const int r0 = ty * 4;
    float acc[4][8];

    if (blockIdx.y == 0) {
        cp4(X, P.p[0] + bc * 6144, 6144, t);
        cp4(W, P.p[2], 12288, t);
        __syncthreads();
        zero_acc8(acc);
        gemm_tile<96>(X, W, acc, tx, ty);
        {
            const float aK = P.p[18][0];
            const float* bk1 = P.p[3];
            #pragma unroll
            for (int i = 0; i < 4; ++i) {
                float v[8];
                #pragma unroll
                for (int j = 0; j < 8; ++j) {
                    int c = colidx(tx, j);
                    float x = acc[i][j] + bk1[c];
                    v[j] = x >= 0.f ? x : aK * x;
                }
                store_row4(T1, r0 + i, tx, v);
            }
        }
        __syncthreads();
        cp4(W, P.p[4], 16384, t);
        __syncthreads();
        zero_acc8(acc);
        gemm_tile<128>(T1, W, acc, tx, ty);
        {
            const float* bk2 = P.p[5];
            const float* gK  = P.p[20];
            const float* beK = P.p[21];
            #pragma unroll
            for (int i = 0; i < 4; ++i) {
                float v[8]; float s1 = 0.f, s2 = 0.f;
                #pragma unroll
                for (int j = 0; j < 8; ++j) {
                    int c = colidx(tx, j);
                    float x = tanha(acc[i][j] + bk2[c]);
                    v[j] = x; s1 += x; s2 += x * x;
                }
                #pragma unroll
                for (int off = 8; off >= 1; off >>= 1) {
                    s1 += __shfl_xor_sync(0xffffffffu, s1, off);
                    s2 += __shfl_xor_sync(0xffffffffu, s2, off);
                }
                float m  = s1 * (1.f / 128.f);
                float va = s2 * (1.f / 128.f) - m * m;
                float rs = rsqrtf(va + 1e-5f);
                #pragma unroll
                for (int j = 0; j < 8; ++j) {
                    int c = colidx(tx, j);
                    v[j] = (v[j] - m) * rs * gK[c] + beK[c];
                }
                store_row4(T2, r0 + i, tx, v);
            }
        }
        __syncthreads();
        cp4(W, P.p[6], 16384, t);
        __syncthreads();
        zero_acc8(acc);
        gemm_tile<128>(T2, W, acc, tx, ty);
        {
            const float* bk3 = P.p[7];
            float* kout = g_keys + bc * 8192;
            #pragma unroll
            for (int i = 0; i < 4; ++i) {
                float v[8];
                #pragma unroll
                for (int j = 0; j < 8; ++j) v[j] = acc[i][j] + bk3[colidx(tx, j)];
                store_row4(T1, r0 + i, tx, v);
                store_row4(kout, r0 + i, tx, v);
            }
        }
        __syncthreads();
        cp4(W, P.p[12] + 16384, 16384, t);
        __syncthreads();
        zero_acc8(acc);
        gemm_tile<128>(T1, W, acc, tx, ty);
        {
            float* hkout = g_hk + bc * 8192;
            #pragma unroll
            for (int i = 0; i < 4; ++i) {
                float v[8];
                #pragma unroll
                for (int j = 0; j < 8; ++j) v[j] = acc[i][j];
                store_row4(hkout, r0 + i, tx, v);
            }
        }
    } else {
        cp4(X, P.p[1] + bc * 6144, 6144, t);
        cp4(W, P.p[8], 12288, t);
        __syncthreads();
        zero_acc8(acc);
        gemm_tile<96>(X, W, acc, tx, ty);
        {
            const float* bq1 = P.p[9];
            #pragma unroll
            for (int i = 0; i < 4; ++i) {
                float v[8];
                #pragma unroll
                for (int j = 0; j < 8; ++j) v[j] = tanha(acc[i][j] + bq1[colidx(tx, j)]);
                store_row4(T1, r0 + i, tx, v);
            }
        }
        __syncthreads();
        cp4(W, P.p[10], 16384, t);
        __syncthreads();
        zero_acc8(acc);
        gemm_tile<128>(T1, W, acc, tx, ty);
        {
            const float* bq2 = P.p[11];
            float* qout = g_queries + bc * 8192;
            #pragma unroll
            for (int i = 0; i < 4; ++i) {
                float v[8];
                #pragma unroll
                for (int j = 0; j < 8; ++j) v[j] = acc[i][j] + bq2[colidx(tx, j)];
                store_row4(T2, r0 + i, tx, v);
                store_row4(qout, r0 + i, tx, v);
            }
        }
        __syncthreads();
        cp4(W, P.p[12], 16384, t);
        __syncthreads();
        zero_acc8(acc);
        gemm_tile<128>(T2, W, acc, tx, ty);
        {
            float* hqout = g_hq + bc * 8192;
            #pragma unroll
            for (int i = 0; i < 4; ++i) {
                float v[8];
                #pragma unroll
                for (int j = 0; j < 8; ++j) v[j] = acc[i][j];
                store_row4(hqout, r0 + i, tx, v);
            }
        }
    }
}

// =====================================================================
// Kernel A2: logits + softmax over n (axis 2) + attn row sums. grid 64
// =====================================================================
__global__ __launch_bounds__(256) void kA2(Params P) {
    extern __shared__ float sm[];
    float* Kp = sm;
    float* Q  = sm + 8256;
    float* L  = Q + 8256;
    const int t = threadIdx.x, tx = t & 15, ty = t >> 4;
    const int bc = blockIdx.x;

    for (int i = t; i < 8192; i += NTHREADS) {
        int r = i >> 7, c = i & 127;
        Kp[r * 129 + c] = g_keys[bc * 8192 + i];
        Q [r * 129 + c] = g_queries[bc * 8192 + i];
    }
    __syncthreads();

    float acc[4][4];
    #pragma unroll
    for (int i = 0; i < 4; ++i)
        #pragma unroll
        for (int j = 0; j < 4; ++j) acc[i][j] = 0.f;
    #pragma unroll 4
    for (int k = 0; k < 128; ++k) {
        float a[4], b[4];
        #pragma unroll
        for (int i = 0; i < 4; ++i) a[i] = Kp[(ty * 4 + i) * 129 + k];
        #pragma unroll
        for (int j = 0; j < 4; ++j) b[j] = Q[(tx * 4 + j) * 129 + k];
        #pragma unroll
        for (int i = 0; i < 4; ++i)
            #pragma unroll
            for (int j = 0; j < 4; ++j) acc[i][j] = fmaf(a[i], b[j], acc[i][j]);
    }
    #pragma unroll
    for (int i = 0; i < 4; ++i)
        #pragma unroll
        for (int j = 0; j < 4; ++j) L[(ty * 4 + i) * 65 + tx * 4 + j] = acc[i][j];
    __syncthreads();

    if (t < 64) {
        int m = t;
        float mx = -1e30f;
        for (int n = 0; n < 64; ++n) mx = fmaxf(mx, L[n * 65 + m]);
        float s = 0.f;
        for (int n = 0; n < 64; ++n) { float e = expf(L[n * 65 + m] - mx); L[n * 65 + m] = e; s += e; }
        float inv = 1.f / s;
        for (int n = 0; n < 64; ++n) L[n * 65 + m] *= inv;
    }
    __syncthreads();
    if (t < 64) {
        int n = t; float s = 0.f;
        for (int m = 0; m < 64; ++m) {
            float v = L[n * 65 + m];
            g_attn[bc * 4096 + n * 64 + m] = v;
            s += v;
        }
        g_asum[bc * 64 + n] = s;
    }
}

// =====================================================================
// Kernel B (persistent, dual-group HMMA, fp16 2-chain, lean phases):
// grid 148 x 512. 2 barriers/item; hk + attn read direct from gmem;
// f16x2 packed converts; folded-LN epilogue.
// =====================================================================
// byte offsets within dynamic smem
#define KB_WHI    0u               // 34816 B (fp16 W)
#define KB_A      34816u           // + group*69632: Ahi; Alo = +34816
#define KB_CONST  174080u          // bv1s, bv2s, gvs, bevs (128 floats each)
#define KB_RED    176128u          // + group*4096 (8 warps x 128 floats)
#define KB_SMEM_BYTES 184320

__global__ __launch_bounds__(512, 1) void kB(Params P) {
    extern __shared__ char smc[];
    const int t = threadIdx.x;
    const int wid = t >> 5, l = t & 31;
    const int group = wid >> 3;         // 0 or 1
    const int gt = t & 255;             // thread within group
    const int gw = wid & 7;             // warp within group
    const int gid = group + 1;          // named barrier id

    float* bv1s = reinterpret_cast<float*>(smc + KB_CONST);
    float* bv2s = bv1s + 128;
    float* gvs  = bv2s + 128;
    float* bevs = gvs + 128;
    float* red  = reinterpret_cast<float*>(smc + KB_RED + group * 4096u);

    unsigned short* Ahi = reinterpret_cast<unsigned short*>(smc + KB_A + group * 69632u);
    unsigned short* Alo = reinterpret_cast<unsigned short*>(reinterpret_cast<char*>(Ahi) + 34816);

    // ---- one-time staging: W fp16 + const vectors (all 512 threads) ----
    {
        const float4* s0 = reinterpret_cast<const float4*>(g_Wh);
        float4* d0 = reinterpret_cast<float4*>(smc + KB_WHI);
        for (int i = t; i < 2176; i += 512) d0[i] = s0[i];
        if (t < 128) {
            bv1s[t] = P.p[13][t];
            bv2s[t] = P.p[15][t];
            gvs[t]  = P.p[22][t];
            bevs[t] = P.p[23][t];
        }
    }
    __syncthreads();

    const float aV = P.p[19][0];
    const unsigned sbase = smem_u32(smc);
    const unsigned aHiAddr = sbase + KB_A + group * 69632u
                           + ((gw * 16 + (l & 15)) * 136) * 2 + (l >> 4) * 16;
    const unsigned aLoAddr = aHiAddr + 34816;
    const unsigned bRow = (l & 7) + ((l >> 4) & 1) * 8;
    const unsigned bAddr = sbase + KB_WHI + (bRow * 136) * 2 + ((l >> 3) & 1) * 16;

    const int qr = l >> 2, qc = l & 3;

    for (int item = blockIdx.x * 2 + group; item < 2048; item += 296) {
        const int bc = item >> 5;
        const int n0 = (item & 31) * 2;

        // ---- build A tile (rows = n_l*64+m, cols = k), fp16 hi/lo ----
        {
            const int r = gt >> 1, ac = gt & 1;
            const int m = r & 63, nl = r >> 6;
            const float* hq = g_hq + bc * 8192 + m * 128 + ac * 64;
            const float* hk = g_hk + (bc * 64 + n0 + nl) * 128 + ac * 64;
            const float* bv = bv1s + ac * 64;
            unsigned short* ph = Ahi + r * 136 + ac * 64;
            unsigned short* pl = Alo + r * 136 + ac * 64;
            #pragma unroll 4
            for (int j = 0; j < 16; ++j) {
                float4 h  = *reinterpret_cast<const float4*>(hq + j * 4);
                float4 kk = *reinterpret_cast<const float4*>(hk + j * 4);
                float4 bb = *reinterpret_cast<const float4*>(bv + j * 4);
                float a0 = h.x + kk.x + bb.x; a0 = a0 >= 0.f ? a0 : aV * a0;
                float a1 = h.y + kk.y + bb.y; a1 = a1 >= 0.f ? a1 : aV * a1;
                float a2 = h.z + kk.z + bb.z; a2 = a2 >= 0.f ? a2 : aV * a2;
                float a3 = h.w + kk.w + bb.w; a3 = a3 >= 0.f ? a3 : aV * a3;
                __half2 h01 = __floats2half2_rn(a0, a1);
                __half2 h23 = __floats2half2_rn(a2, a3);
                float2 f01 = __half22float2(h01);
                float2 f23 = __half22float2(h23);
                __half2 l01 = __floats2half2_rn(a0 - f01.x, a1 - f01.y);
                __half2 l23 = __floats2half2_rn(a2 - f23.x, a3 - f23.y);
                uint2 vh, vl;
                vh.x = *reinterpret_cast<unsigned*>(&h01);
                vh.y = *reinterpret_cast<unsigned*>(&h23);
                vl.x = *reinterpret_cast<unsigned*>(&l01);
                vl.y = *reinterpret_cast<unsigned*>(&l23);
                *reinterpret_cast<uint2*>(ph + j * 4) = vh;
                *reinterpret_cast<uint2*>(pl + j * 4) = vl;
            }
        }
        GBAR(gid);

        // ---- GEMM: 8 warps x (16m x 128n), K=128, 2 chains (Ah+Al)@Wh ----
        float acc[16][4];
        #pragma unroll
        for (int nt = 0; nt < 16; ++nt)
            #pragma unroll
            for (int j = 0; j < 4; ++j) acc[nt][j] = 0.f;

        #pragma unroll
        for (int ks = 0; ks < 8; ++ks) {
            unsigned ah[4], al[4];
            LDSM_X4(ah, aHiAddr + ks * 32);
            LDSM_X4(al, aLoAddr + ks * 32);
            #pragma unroll
            for (int p = 0; p < 8; ++p) {
                unsigned bh[4];
                LDSM_X4(bh, bAddr + p * 4352 + ks * 32);
                MMA16816(acc[2*p],     ah, bh[0], bh[1]);
                MMA16816(acc[2*p + 1], ah, bh[2], bh[3]);
                MMA16816(acc[2*p],     al, bh[0], bh[1]);
                MMA16816(acc[2*p + 1], al, bh[2], bh[3]);
            }
        }

        // ---- epilogue: tanh.approx + folded LN + attn weighting ----
        {
            float s1a = 0.f, s2a = 0.f, s1b = 0.f, s2b = 0.f;
            #pragma unroll
            for (int nt = 0; nt < 16; ++nt) {
                int c0 = nt * 8 + qc * 2;
                float x0 = tanha(acc[nt][0] + bv2s[c0]);
                float x1 = tanha(acc[nt][1] + bv2s[c0 + 1]);
                float x2 = tanha(acc[nt][2] + bv2s[c0]);
                float x3 = tanha(acc[nt][3] + bv2s[c0 + 1]);
                acc[nt][0] = x0; acc[nt][1] = x1; acc[nt][2] = x2; acc[nt][3] = x3;
                s1a += x0 + x1; s2a += x0 * x0 + x1 * x1;
                s1b += x2 + x3; s2b += x2 * x2 + x3 * x3;
            }
            #pragma unroll
            for (int off = 1; off <= 2; off <<= 1) {
                s1a += __shfl_xor_sync(0xffffffffu, s1a, off);
                s2a += __shfl_xor_sync(0xffffffffu, s2a, off);
                s1b += __shfl_xor_sync(0xffffffffu, s1b, off);
                s2b += __shfl_xor_sync(0xffffffffu, s2b, off);
            }
            float mua = s1a * (1.f / 128.f);
            float rsa = rsqrtf(s2a * (1.f / 128.f) - mua * mua + 1e-5f);
            float mub = s1b * (1.f / 128.f);
            float rsb = rsqrtf(s2b * (1.f / 128.f) - mub * mub + 1e-5f);

            // attn weights direct from gmem (L2): rows m0, m0+8 of n = n0+(gw>>2)
            const int nn = n0 + (gw >> 2);
            const int m0 = (gw & 3) * 16 + qr;
            const float* ab = g_attn + bc * 4096 + nn * 64;
            float wa = ab[m0], wb = ab[m0 + 8];

            float aco0 = wa * rsa, aco1 = wb * rsb;
            float bsum = fmaf(aco0, mua, aco1 * mub);
            float ws = wa + wb;

            float part[32];
            #pragma unroll
            for (int nt = 0; nt < 16; ++nt) {
                #pragma unroll
                for (int jj = 0; jj < 2; ++jj) {
                    int c = nt * 8 + qc * 2 + jj;
                    float inner = fmaf(aco0, acc[nt][jj],
                                  fmaf(aco1, acc[nt][jj + 2], -bsum));
                    part[nt * 2 + jj] = fmaf(gvs[c], inner, bevs[c] * ws);
                }
            }
            #pragma unroll
            for (int off = 4; off <= 16; off <<= 1)
                #pragma unroll
                for (int s = 0; s < 32; ++s)
                    part[s] += __shfl_xor_sync(0xffffffffu, part[s], off);
            if (l < 4) {
                #pragma unroll
                for (int nt = 0; nt < 16; ++nt) {
                    red[gw * 128 + nt * 8 + l * 2 + 0] = part[nt * 2 + 0];
                    red[gw * 128 + nt * 8 + l * 2 + 1] = part[nt * 2 + 1];
                }
            }
        }
        GBAR(gid);

        // ---- final: combine 4 m-warps per n, store g_G ----
        {
            const int nl = gt >> 7, c = gt & 127;
            const float* rb = red + nl * 512 + c;
            g_G[(bc * 64 + n0 + nl) * 128 + c] = rb[0] + rb[128] + rb[256] + rb[384];
        }
        // no barrier: red reads complete before this warp's next epilogue,
        // which is gated by the post-build GBAR of the next item.
    }
}

// =====================================================================
// Kernel C: out = g @ Wv3 + asum * bv3. grid (64, 2) column halves
// =====================================================================
__global__ __launch_bounds__(256) void kC(Params P, float* __restrict__ out) {
    extern __shared__ float sm[];
    float* A = sm;          // 8192
    float* W = sm + 8192;   // 8192 (128 x 64 half)
    const int t = threadIdx.x, tx = t & 15, ty = t >> 4;
    const int bc = blockIdx.x, half = blockIdx.y;
    const int r0 = ty * 4;

    cp4(A, g_G + bc * 8192, 8192, t);
    {
        const float* Wv3 = P.p[16];
        for (int i = t; i < 8192; i += NTHREADS) {
            int k = i >> 6, c = i & 63;
            W[i] = Wv3[k * 128 + half * 64 + c];
        }
    }
    __syncthreads();

    float acc[4][4];
    #pragma unroll
    for (int i = 0; i < 4; ++i)
        #pragma unroll
        for (int j = 0; j < 4; ++j) acc[i][j] = 0.f;
    #pragma unroll 4
    for (int k = 0; k < 128; ++k) {
        float a[4];
        #pragma unroll
        for (int i = 0; i < 4; ++i) a[i] = A[(r0 + i) * 128 + k];
        float4 b4 = *reinterpret_cast<const float4*>(W + k * 64 + tx * 4);
        float bb[4] = {b4.x, b4.y, b4.z, b4.w};
        #pragma unroll
        for (int i = 0; i < 4; ++i)
            #pragma unroll
            for (int j = 0; j < 4; ++j)
                acc[i][j] = fmaf(a[i], bb[j], acc[i][j]);
    }

    const float* bv3 = P.p[17];
    #pragma unroll
    for (int i = 0; i < 4; ++i) {
        int r = r0 + i;
        float as = g_asum[bc * 64 + r];
        float4 v;
        int cb = half * 64 + tx * 4;
        v.x = acc[i][0] + as * bv3[cb + 0];
        v.y = acc[i][1] + as * bv3[cb + 1];
        v.z = acc[i][2] + as * bv3[cb + 2];
        v.w = acc[i][3] + as * bv3[cb + 3];
        *reinterpret_cast<float4*>(out + (bc * 64 + r) * 128 + cb) = v;
    }
}

// =====================================================================
extern "C" void kernel_launch(void* const* d_in, const int* in_sizes, int n_in,
                              void* d_out, int out_size) {
    (void)in_sizes; (void)n_in; (void)out_size;
    Params P;
    for (int i = 0; i < 24; ++i) P.p[i] = reinterpret_cast<const float*>(d_in[i]);

    const int SMEM_A1 = (6144 + 16384 + 8192 + 8192) * 4;
    const int SMEM_A2 = (8256 + 8256 + 64 * 65) * 4;
    const int SMEM_B  = KB_SMEM_BYTES;
    const int SMEM_C  = (8192 + 8192) * 4;

    cudaFuncSetAttribute(kA1, cudaFuncAttributeMaxDynamicSharedMemorySize, SMEM_A1);
    cudaFuncSetAttribute(kA2, cudaFuncAttributeMaxDynamicSharedMemorySize, SMEM_A2);
    cudaFuncSetAttribute(kB,  cudaFuncAttributeMaxDynamicSharedMemorySize, SMEM_B);
    cudaFuncSetAttribute(kC,  cudaFuncAttributeMaxDynamicSharedMemorySize, SMEM_C);

    kW <<<64, 256>>>(P);
    kA1<<<dim3(64, 2), NTHREADS, SMEM_A1>>>(P);
    kA2<<<64, NTHREADS, SMEM_A2>>>(P);
    kB <<<148, 512, SMEM_B>>>(P);
    kC <<<dim3(64, 2), NTHREADS, SMEM_C>>>(P, reinterpret_cast<float*>(d_out));
}

// round 12
// speedup vs baseline: 1.2110x; 1.1439x over previous
#include <cuda_runtime.h>
#include <cuda_bf16.h>
#include <cuda_fp16.h>

#define NTHREADS 256

struct Params { const float* p[24]; };

// ---- scratch (static device globals; no allocation) ----
__device__ float g_keys   [64*64*128];
__device__ float g_queries[64*64*128];
__device__ float g_hk     [64*64*128];
__device__ float g_hq     [64*64*128];
__device__ float g_attn   [64*64*64];
__device__ float g_asum   [64*64];
__device__ float g_G      [64*64*128];
// Wv2^T as [n=s_out][k=s_in], fp16, rows padded to 136 elems (272B)
__device__ __align__(16) unsigned short g_Wh[128*136];

__device__ __forceinline__ float tanha(float x) {
    float y;
    asm("tanh.approx.f32 %0, %1;" : "=f"(y) : "f"(x));
    return y;
}

__device__ __forceinline__ void cp4(float* dst, const float* src, int n, int t) {
    for (int i = t*4; i < n; i += NTHREADS*4)
        *reinterpret_cast<float4*>(dst + i) = *reinterpret_cast<const float4*>(src + i);
}

__device__ __forceinline__ int colidx(int tx, int j) { return j < 4 ? tx*4 + j : 60 + tx*4 + j; }

__device__ __forceinline__ void zero_acc8(float acc[4][8]) {
    #pragma unroll
    for (int i = 0; i < 4; ++i)
        #pragma unroll
        for (int j = 0; j < 8; ++j) acc[i][j] = 0.f;
}

template<int K>
__device__ __forceinline__ void gemm_tile(const float* __restrict__ A, const float* __restrict__ W,
                                          float acc[4][8], int tx, int ty) {
    const int r0 = ty * 4;
    const int ca = tx * 4, cb = 64 + tx * 4;
    #pragma unroll 4
    for (int k = 0; k < K; ++k) {
        float aa[4];
        #pragma unroll
        for (int i = 0; i < 4; ++i) aa[i] = A[(r0 + i) * K + k];
        float4 b0 = *reinterpret_cast<const float4*>(W + k * 128 + ca);
        float4 b1 = *reinterpret_cast<const float4*>(W + k * 128 + cb);
        float bb[8] = {b0.x, b0.y, b0.z, b0.w, b1.x, b1.y, b1.z, b1.w};
        #pragma unroll
        for (int i = 0; i < 4; ++i)
            #pragma unroll
            for (int j = 0; j < 8; ++j)
                acc[i][j] = fmaf(aa[i], bb[j], acc[i][j]);
    }
}

__device__ __forceinline__ void store_row4(float* base, int row, int tx, const float v[8]) {
    *reinterpret_cast<float4*>(base + row * 128 + tx * 4)      = make_float4(v[0], v[1], v[2], v[3]);
    *reinterpret_cast<float4*>(base + row * 128 + 64 + tx * 4) = make_float4(v[4], v[5], v[6], v[7]);
}

__device__ __forceinline__ unsigned smem_u32(const void* p) {
    unsigned a;
    asm("{ .reg .u64 t; cvta.to.shared.u64 t, %1; cvt.u32.u64 %0, t; }" : "=r"(a) : "l"(p));
    return a;
}

#define LDSM_X4(r, addr)                                                       \
    asm volatile("ldmatrix.sync.aligned.m8n8.x4.shared.b16 {%0,%1,%2,%3}, [%4];" \
        : "=r"((r)[0]), "=r"((r)[1]), "=r"((r)[2]), "=r"((r)[3]) : "r"(addr))

#define MMA16816(d, a, b0, b1)                                                 \
    asm volatile("mma.sync.aligned.m16n8k16.row.col.f32.f16.f16.f32 "          \
        "{%0,%1,%2,%3}, {%4,%5,%6,%7}, {%8,%9}, {%0,%1,%2,%3};"                \
        : "+f"((d)[0]), "+f"((d)[1]), "+f"((d)[2]), "+f"((d)[3])               \
        : "r"((a)[0]), "r"((a)[1]), "r"((a)[2]), "r"((a)[3]), "r"(b0), "r"(b1))

#define GBAR(gid)                                                              \
    asm volatile("bar.sync %0, %1;" :: "r"(gid), "r"(256u) : "memory")

#define CPA16(dst, src)                                                        \
    asm volatile("cp.async.cg.shared.global [%0], [%1], 16;"                   \
        :: "r"(dst), "l"(src) : "memory")
#define CPA_COMMIT() asm volatile("cp.async.commit_group;" ::: "memory")
#define CPA_WAIT()   asm volatile("cp.async.wait_group 0;" ::: "memory")

// =====================================================================
// Kernel kW: precompute Wv2^T fp16 into padded [128][136]. grid 64
// =====================================================================
__global__ __launch_bounds__(256) void kW(Params P) {
    int t = blockIdx.x * 256 + threadIdx.x;
    const float* Wv2 = P.p[14];
    if (t < 16384) {
        int n = t >> 7, k = t & 127;
        g_Wh[n * 136 + k] = __half_as_ushort(__float2half_rn(Wv2[k * 128 + n]));
    }
}

// =====================================================================
// Kernel A1: keys / queries MLPs + hk, hq projections. grid (64 bc, 2 paths)
// =====================================================================
__global__ __launch_bounds__(256) void kA1(Params P) {
    extern __shared__ float sm[];
    float* X  = sm;
    float* W  = sm + 6144;
    float* T1 = W + 16384;
    float* T2 = T1 + 8192;
    const int t = threadIdx.x, tx = t & 15, ty = t >> 4;
    const int bc = blockIdx.x;
    const int r0 = ty * 4;
    float acc[4][8];

    if (blockIdx.y == 0) {
        cp4(X, P.p[0] + bc * 6144, 6144, t);
        cp4(W, P.p[2], 12288, t);
        __syncthreads();
        zero_acc8(acc);
        gemm_tile<96>(X, W, acc, tx, ty);
        {
            const float aK = P.p[18][0];
            const float* bk1 = P.p[3];
            #pragma unroll
            for (int i = 0; i < 4; ++i) {
                float v[8];
                #pragma unroll
                for (int j = 0; j < 8; ++j) {
                    int c = colidx(tx, j);
                    float x = acc[i][j] + bk1[c];
                    v[j] = x >= 0.f ? x : aK * x;
                }
                store_row4(T1, r0 + i, tx, v);
            }
        }
        __syncthreads();
        cp4(W, P.p[4], 16384, t);
        __syncthreads();
        zero_acc8(acc);
        gemm_tile<128>(T1, W, acc, tx, ty);
        {
            const float* bk2 = P.p[5];
            const float* gK  = P.p[20];
            const float* beK = P.p[21];
            #pragma unroll
            for (int i = 0; i < 4; ++i) {
                float v[8]; float s1 = 0.f, s2 = 0.f;
                #pragma unroll
                for (int j = 0; j < 8; ++j) {
                    int c = colidx(tx, j);
                    float x = tanha(acc[i][j] + bk2[c]);
                    v[j] = x; s1 += x; s2 += x * x;
                }
                #pragma unroll
                for (int off = 8; off >= 1; off >>= 1) {
                    s1 += __shfl_xor_sync(0xffffffffu, s1, off);
                    s2 += __shfl_xor_sync(0xffffffffu, s2, off);
                }
                float m  = s1 * (1.f / 128.f);
                float va = s2 * (1.f / 128.f) - m * m;
                float rs = rsqrtf(va + 1e-5f);
                #pragma unroll
                for (int j = 0; j < 8; ++j) {
                    int c = colidx(tx, j);
                    v[j] = (v[j] - m) * rs * gK[c] + beK[c];
                }
                store_row4(T2, r0 + i, tx, v);
            }
        }
        __syncthreads();
        cp4(W, P.p[6], 16384, t);
        __syncthreads();
        zero_acc8(acc);
        gemm_tile<128>(T2, W, acc, tx, ty);
        {
            const float* bk3 = P.p[7];
            float* kout = g_keys + bc * 8192;
            #pragma unroll
            for (int i = 0; i < 4; ++i) {
                float v[8];
                #pragma unroll
                for (int j = 0; j < 8; ++j) v[j] = acc[i][j] + bk3[colidx(tx, j)];
                store_row4(T1, r0 + i, tx, v);
                store_row4(kout, r0 + i, tx, v);
            }
        }
        __syncthreads();
        cp4(W, P.p[12] + 16384, 16384, t);
        __syncthreads();
        zero_acc8(acc);
        gemm_tile<128>(T1, W, acc, tx, ty);
        {
            float* hkout = g_hk + bc * 8192;
            #pragma unroll
            for (int i = 0; i < 4; ++i) {
                float v[8];
                #pragma unroll
                for (int j = 0; j < 8; ++j) v[j] = acc[i][j];
                store_row4(hkout, r0 + i, tx, v);
            }
        }
    } else {
        cp4(X, P.p[1] + bc * 6144, 6144, t);
        cp4(W, P.p[8], 12288, t);
        __syncthreads();
        zero_acc8(acc);
        gemm_tile<96>(X, W, acc, tx, ty);
        {
            const float* bq1 = P.p[9];
            #pragma unroll
            for (int i = 0; i < 4; ++i) {
                float v[8];
                #pragma unroll
                for (int j = 0; j < 8; ++j) v[j] = tanha(acc[i][j] + bq1[colidx(tx, j)]);
                store_row4(T1, r0 + i, tx, v);
            }
        }
        __syncthreads();
        cp4(W, P.p[10], 16384, t);
        __syncthreads();
        zero_acc8(acc);
        gemm_tile<128>(T1, W, acc, tx, ty);
        {
            const float* bq2 = P.p[11];
            float* qout = g_queries + bc * 8192;
            #pragma unroll
            for (int i = 0; i < 4; ++i) {
                float v[8];
                #pragma unroll
                for (int j = 0; j < 8; ++j) v[j] = acc[i][j] + bq2[colidx(tx, j)];
                store_row4(T2, r0 + i, tx, v);
                store_row4(qout, r0 + i, tx, v);
            }
        }
        __syncthreads();
        cp4(W, P.p[12], 16384, t);
        __syncthreads();
        zero_acc8(acc);
        gemm_tile<128>(T2, W, acc, tx, ty);
        {
            float* hqout = g_hq + bc * 8192;
            #pragma unroll
            for (int i = 0; i < 4; ++i) {
                float v[8];
                #pragma unroll
                for (int j = 0; j < 8; ++j) v[j] = acc[i][j];
                store_row4(hqout, r0 + i, tx, v);
            }
        }
    }
}

// =====================================================================
// Kernel A2: logits + softmax over n (axis 2) + attn row sums. grid 64
// =====================================================================
__global__ __launch_bounds__(256) void kA2(Params P) {
    extern __shared__ float sm[];
    float* Kp = sm;
    float* Q  = sm + 8256;
    float* L  = Q + 8256;
    const int t = threadIdx.x, tx = t & 15, ty = t >> 4;
    const int bc = blockIdx.x;

    for (int i = t; i < 8192; i += NTHREADS) {
        int r = i >> 7, c = i & 127;
        Kp[r * 129 + c] = g_keys[bc * 8192 + i];
        Q [r * 129 + c] = g_queries[bc * 8192 + i];
    }
    __syncthreads();

    float acc[4][4];
    #pragma unroll
    for (int i = 0; i < 4; ++i)
        #pragma unroll
        for (int j = 0; j < 4; ++j) acc[i][j] = 0.f;
    #pragma unroll 4
    for (int k = 0; k < 128; ++k) {
        float a[4], b[4];
        #pragma unroll
        for (int i = 0; i < 4; ++i) a[i] = Kp[(ty * 4 + i) * 129 + k];
        #pragma unroll
        for (int j = 0; j < 4; ++j) b[j] = Q[(tx * 4 + j) * 129 + k];
        #pragma unroll
        for (int i = 0; i < 4; ++i)
            #pragma unroll
            for (int j = 0; j < 4; ++j) acc[i][j] = fmaf(a[i], b[j], acc[i][j]);
    }
    #pragma unroll
    for (int i = 0; i < 4; ++i)
        #pragma unroll
        for (int j = 0; j < 4; ++j) L[(ty * 4 + i) * 65 + tx * 4 + j] = acc[i][j];
    __syncthreads();

    if (t < 64) {
        int m = t;
        float mx = -1e30f;
        for (int n = 0; n < 64; ++n) mx = fmaxf(mx, L[n * 65 + m]);
        float s = 0.f;
        for (int n = 0; n < 64; ++n) { float e = expf(L[n * 65 + m] - mx); L[n * 65 + m] = e; s += e; }
        float inv = 1.f / s;
        for (int n = 0; n < 64; ++n) L[n * 65 + m] *= inv;
    }
    __syncthreads();
    if (t < 64) {
        int n = t; float s = 0.f;
        for (int m = 0; m < 64; ++m) {
            float v = L[n * 65 + m];
            g_attn[bc * 4096 + n * 64 + m] = v;
            s += v;
        }
        g_asum[bc * 64 + n] = s;
    }
}

// =====================================================================
// Kernel B (persistent, dual-group HMMA, fp16 SINGLE chain + cp.async
// prefetch of hq/hk): grid 148 x 512. 2 barriers/item.
// =====================================================================
// byte offsets within dynamic smem
#define KB_WH    0u                 // 34816 (fp16 W)
#define KB_A     34816u             // + group*34816 (Ahi only)
#define KB_STG   104448u            // + group*33792: hq(32768) hk(1024)
#define KB_CONST 172032u            // bv1s, bv2s, gvs, bevs (128 floats each)
#define KB_RED   174080u            // + group*4096 (8 warps x 128 floats)
#define KB_SMEM_BYTES 182272

__global__ __launch_bounds__(512, 1) void kB(Params P) {
    extern __shared__ char smc[];
    const int t = threadIdx.x;
    const int wid = t >> 5, l = t & 31;
    const int group = wid >> 3;         // 0 or 1
    const int gt = t & 255;             // thread within group
    const int gw = wid & 7;             // warp within group
    const int gid = group + 1;          // named barrier id

    float* bv1s = reinterpret_cast<float*>(smc + KB_CONST);
    float* bv2s = bv1s + 128;
    float* gvs  = bv2s + 128;
    float* bevs = gvs + 128;
    float* red  = reinterpret_cast<float*>(smc + KB_RED + group * 4096u);
    float* stg  = reinterpret_cast<float*>(smc + KB_STG + group * 33792u);

    unsigned short* Ahi = reinterpret_cast<unsigned short*>(smc + KB_A + group * 34816u);

    // ---- one-time staging: W fp16 + const vectors (all 512 threads) ----
    {
        const float4* s0 = reinterpret_cast<const float4*>(g_Wh);
        float4* d0 = reinterpret_cast<float4*>(smc + KB_WH);
        for (int i = t; i < 2176; i += 512) d0[i] = s0[i];
        if (t < 128) {
            bv1s[t] = P.p[13][t];
            bv2s[t] = P.p[15][t];
            gvs[t]  = P.p[22][t];
            bevs[t] = P.p[23][t];
        }
    }

    const float aV = P.p[19][0];
    const unsigned sbase = smem_u32(smc);
    const unsigned stgAddr = sbase + KB_STG + group * 33792u;
    const unsigned aAddr = sbase + KB_A + group * 34816u
                         + ((gw * 16 + (l & 15)) * 136) * 2 + (l >> 4) * 16;
    const unsigned bRow = (l & 7) + ((l >> 4) & 1) * 8;
    const unsigned bAddr = sbase + KB_WH + (bRow * 136) * 2 + ((l >> 3) & 1) * 16;

    const int qr = l >> 2, qc = l & 3;
    const int item0 = blockIdx.x * 2 + group;

    // ---- prologue prefetch: first item's hq + hk into staging ----
    if (item0 < 2048) {
        int nbc = item0 >> 5, nn0 = (item0 & 31) * 2;
        const float* hsrc = g_hq + nbc * 8192;
        #pragma unroll
        for (int k2 = 0; k2 < 8; ++k2) {
            unsigned u = (unsigned)(k2 * 256 + gt);
            CPA16(stgAddr + u * 16, hsrc + u * 4);
        }
        if (gt < 64)
            CPA16(stgAddr + 32768 + gt * 16, g_hk + (nbc * 64 + nn0) * 128 + gt * 4);
    }
    CPA_COMMIT();
    CPA_WAIT();
    __syncthreads();

    for (int item = item0; item < 2048; item += 296) {
        const int bc = item >> 5;
        const int n0 = (item & 31) * 2;

        // ---- build A tile (rows = n_l*64+m, cols = k), fp16, from staging ----
        {
            const int r = gt >> 1, ac = gt & 1;
            const int m = r & 63, nl = r >> 6;
            const float* hq = stg + m * 128 + ac * 64;
            const float* hk = stg + 8192 + nl * 128 + ac * 64;
            const float* bv = bv1s + ac * 64;
            unsigned short* ph = Ahi + r * 136 + ac * 64;
            #pragma unroll 4
            for (int j = 0; j < 16; ++j) {
                float4 h  = *reinterpret_cast<const float4*>(hq + j * 4);
                float4 kk = *reinterpret_cast<const float4*>(hk + j * 4);
                float4 bb = *reinterpret_cast<const float4*>(bv + j * 4);
                float a0 = h.x + kk.x + bb.x; a0 = a0 >= 0.f ? a0 : aV * a0;
                float a1 = h.y + kk.y + bb.y; a1 = a1 >= 0.f ? a1 : aV * a1;
                float a2 = h.z + kk.z + bb.z; a2 = a2 >= 0.f ? a2 : aV * a2;
                float a3 = h.w + kk.w + bb.w; a3 = a3 >= 0.f ? a3 : aV * a3;
                __half2 h01 = __floats2half2_rn(a0, a1);
                __half2 h23 = __floats2half2_rn(a2, a3);
                uint2 vh;
                vh.x = *reinterpret_cast<unsigned*>(&h01);
                vh.y = *reinterpret_cast<unsigned*>(&h23);
                *reinterpret_cast<uint2*>(ph + j * 4) = vh;
            }
        }
        GBAR(gid);

        // ---- issue prefetch for NEXT item (lands during mainloop) ----
        {
            int nitem = item + 296;
            if (nitem < 2048) {
                int nbc = nitem >> 5, nn0 = (nitem & 31) * 2;
                const float* hsrc = g_hq + nbc * 8192;
                #pragma unroll
                for (int k2 = 0; k2 < 8; ++k2) {
                    unsigned u = (unsigned)(k2 * 256 + gt);
                    CPA16(stgAddr + u * 16, hsrc + u * 4);
                }
                if (gt < 64)
                    CPA16(stgAddr + 32768 + gt * 16, g_hk + (nbc * 64 + nn0) * 128 + gt * 4);
            }
            CPA_COMMIT();
        }

        // ---- GEMM: 8 warps x (16m x 128n), K=128, single fp16 chain ----
        float acc[16][4];
        #pragma unroll
        for (int nt = 0; nt < 16; ++nt)
            #pragma unroll
            for (int j = 0; j < 4; ++j) acc[nt][j] = 0.f;

        #pragma unroll
        for (int ks = 0; ks < 8; ++ks) {
            unsigned ah[4];
            LDSM_X4(ah, aAddr + ks * 32);
            #pragma unroll
            for (int p = 0; p < 8; ++p) {
                unsigned bh[4];
                LDSM_X4(bh, bAddr + p * 4352 + ks * 32);
                MMA16816(acc[2*p],     ah, bh[0], bh[1]);
                MMA16816(acc[2*p + 1], ah, bh[2], bh[3]);
            }
        }

        // ---- epilogue: tanh.approx + folded LN + attn weighting ----
        {
            float s1a = 0.f, s2a = 0.f, s1b = 0.f, s2b = 0.f;
            #pragma unroll
            for (int nt = 0; nt < 16; ++nt) {
                int c0 = nt * 8 + qc * 2;
                float x0 = tanha(acc[nt][0] + bv2s[c0]);
                float x1 = tanha(acc[nt][1] + bv2s[c0 + 1]);
                float x2 = tanha(acc[nt][2] + bv2s[c0]);
                float x3 = tanha(acc[nt][3] + bv2s[c0 + 1]);
                acc[nt][0] = x0; acc[nt][1] = x1; acc[nt][2] = x2; acc[nt][3] = x3;
                s1a += x0 + x1; s2a += x0 * x0 + x1 * x1;
                s1b += x2 + x3; s2b += x2 * x2 + x3 * x3;
            }
            #pragma unroll
            for (int off = 1; off <= 2; off <<= 1) {
                s1a += __shfl_xor_sync(0xffffffffu, s1a, off);
                s2a += __shfl_xor_sync(0xffffffffu, s2a, off);
                s1b += __shfl_xor_sync(0xffffffffu, s1b, off);
                s2b += __shfl_xor_sync(0xffffffffu, s2b, off);
            }
            float mua = s1a * (1.f / 128.f);
            float rsa = rsqrtf(s2a * (1.f / 128.f) - mua * mua + 1e-5f);
            float mub = s1b * (1.f / 128.f);
            float rsb = rsqrtf(s2b * (1.f / 128.f) - mub * mub + 1e-5f);

            // attn weights direct from gmem (L2): rows m0, m0+8 of n = n0+(gw>>2)
            const int nn = n0 + (gw >> 2);
            const int m0 = (gw & 3) * 16 + qr;
            const float* ab = g_attn + bc * 4096 + nn * 64;
            float wa = ab[m0], wb = ab[m0 + 8];

            float aco0 = wa * rsa, aco1 = wb * rsb;
            float bsum = fmaf(aco0, mua, aco1 * mub);
            float ws = wa + wb;

            float part[32];
            #pragma unroll
            for (int nt = 0; nt < 16; ++nt) {
                #pragma unroll
                for (int jj = 0; jj < 2; ++jj) {
                    int c = nt * 8 + qc * 2 + jj;
                    float inner = fmaf(aco0, acc[nt][jj],
                                  fmaf(aco1, acc[nt][jj + 2], -bsum));
                    part[nt * 2 + jj] = fmaf(gvs[c], inner, bevs[c] * ws);
                }
            }
            #pragma unroll
            for (int off = 4; off <= 16; off <<= 1)
                #pragma unroll
                for (int s = 0; s < 32; ++s)
                    part[s] += __shfl_xor_sync(0xffffffffu, part[s], off);
            if (l < 4) {
                #pragma unroll
                for (int nt = 0; nt < 16; ++nt) {
                    red[gw * 128 + nt * 8 + l * 2 + 0] = part[nt * 2 + 0];
                    red[gw * 128 + nt * 8 + l * 2 + 1] = part[nt * 2 + 1];
                }
            }
        }
        CPA_WAIT();   // own prefetch ops landed; barrier makes them group-visible
        GBAR(gid);

        // ---- final: combine 4 m-warps per n, store g_G ----
        {
            const int nl = gt >> 7, c = gt & 127;
            const float* rb = red + nl * 512 + c;
            g_G[(bc * 64 + n0 + nl) * 128 + c] = rb[0] + rb[128] + rb[256] + rb[384];
        }
        // no trailing barrier: red reads finish before next epilogue (gated by
        // post-build GBAR); staging reads in next build are ordered by the
        // CPA_WAIT + GBAR above.
    }
}

// =====================================================================
// Kernel C: out = g @ Wv3 + asum * bv3. grid (64, 2) column halves
// =====================================================================
__global__ __launch_bounds__(256) void kC(Params P, float* __restrict__ out) {
    extern __shared__ float sm[];
    float* A = sm;          // 8192
    float* W = sm + 8192;   // 8192 (128 x 64 half)
    const int t = threadIdx.x, tx = t & 15, ty = t >> 4;
    const int bc = blockIdx.x, half = blockIdx.y;
    const int r0 = ty * 4;

    cp4(A, g_G + bc * 8192, 8192, t);
    {
        const float* Wv3 = P.p[16];
        for (int i = t; i < 8192; i += NTHREADS) {
            int k = i >> 6, c = i & 63;
            W[i] = Wv3[k * 128 + half * 64 + c];
        }
    }
    __syncthreads();

    float acc[4][4];
    #pragma unroll
    for (int i = 0; i < 4; ++i)
        #pragma unroll
        for (int j = 0; j < 4; ++j) acc[i][j] = 0.f;
    #pragma unroll 4
    for (int k = 0; k < 128; ++k) {
        float a[4];
        #pragma unroll
        for (int i = 0; i < 4; ++i) a[i] = A[(r0 + i) * 128 + k];
        float4 b4 = *reinterpret_cast<const float4*>(W + k * 64 + tx * 4);
        float bb[4] = {b4.x, b4.y, b4.z, b4.w};
        #pragma unroll
        for (int i = 0; i < 4; ++i)
            #pragma unroll
            for (int j = 0; j < 4; ++j)
                acc[i][j] = fmaf(a[i], bb[j], acc[i][j]);
    }

    const float* bv3 = P.p[17];
    #pragma unroll
    for (int i = 0; i < 4; ++i) {
        int r = r0 + i;
        float as = g_asum[bc * 64 + r];
        float4 v;
        int cb = half * 64 + tx * 4;
        v.x = acc[i][0] + as * bv3[cb + 0];
        v.y = acc[i][1] + as * bv3[cb + 1];
        v.z = acc[i][2] + as * bv3[cb + 2];
        v.w = acc[i][3] + as * bv3[cb + 3];
        *reinterpret_cast<float4*>(out + (bc * 64 + r) * 128 + cb) = v;
    }
}

// =====================================================================
extern "C" void kernel_launch(void* const* d_in, const int* in_sizes, int n_in,
                              void* d_out, int out_size) {
    (void)in_sizes; (void)n_in; (void)out_size;
    Params P;
    for (int i = 0; i < 24; ++i) P.p[i] = reinterpret_cast<const float*>(d_in[i]);

    const int SMEM_A1 = (6144 + 16384 + 8192 + 8192) * 4;
    const int SMEM_A2 = (8256 + 8256 + 64 * 65) * 4;
    const int SMEM_B  = KB_SMEM_BYTES;
    const int SMEM_C  = (8192 + 8192) * 4;

    cudaFuncSetAttribute(kA1, cudaFuncAttributeMaxDynamicSharedMemorySize, SMEM_A1);
    cudaFuncSetAttribute(kA2, cudaFuncAttributeMaxDynamicSharedMemorySize, SMEM_A2);
    cudaFuncSetAttribute(kB,  cudaFuncAttributeMaxDynamicSharedMemorySize, SMEM_B);
    cudaFuncSetAttribute(kC,  cudaFuncAttributeMaxDynamicSharedMemorySize, SMEM_C);

    kW <<<64, 256>>>(P);
    kA1<<<dim3(64, 2), NTHREADS, SMEM_A1>>>(P);
    kA2<<<64, NTHREADS, SMEM_A2>>>(P);
    kB <<<148, 512, SMEM_B>>>(P);
    kC <<<dim3(64, 2), NTHREADS, SMEM_C>>>(P, reinterpret_cast<float*>(d_out));
}

// round 13
// speedup vs baseline: 1.2297x; 1.0154x over previous
#include <cuda_runtime.h>
#include <cuda_bf16.h>
#include <cuda_fp16.h>

#define NTHREADS 256

struct Params { const float* p[24]; };

// ---- scratch (static device globals; no allocation) ----
__device__ float g_keys   [64*64*128];
__device__ float g_queries[64*64*128];
__device__ float g_hk     [64*64*128];   // stores hk + bv1 (folded in kA1)
__device__ float g_hq     [64*64*128];
__device__ float g_attn   [64*64*64];
__device__ float g_asum   [64*64];
__device__ float g_G      [64*64*128];
// Wv2^T / Wv3^T as [n][k], fp16, rows padded to 136 elems (272B)
__device__ __align__(16) unsigned short g_Wh [128*136];
__device__ __align__(16) unsigned short g_W3h[128*136];

__device__ __forceinline__ float tanha(float x) {
    float y;
    asm("tanh.approx.f32 %0, %1;" : "=f"(y) : "f"(x));
    return y;
}

__device__ __forceinline__ void cp4(float* dst, const float* src, int n, int t) {
    for (int i = t*4; i < n; i += NTHREADS*4)
        *reinterpret_cast<float4*>(dst + i) = *reinterpret_cast<const float4*>(src + i);
}

__device__ __forceinline__ int colidx(int tx, int j) { return j < 4 ? tx*4 + j : 60 + tx*4 + j; }

__device__ __forceinline__ void zero_acc8(float acc[4][8]) {
    #pragma unroll
    for (int i = 0; i < 4; ++i)
        #pragma unroll
        for (int j = 0; j < 8; ++j) acc[i][j] = 0.f;
}

template<int K>
__device__ __forceinline__ void gemm_tile(const float* __restrict__ A, const float* __restrict__ W,
                                          float acc[4][8], int tx, int ty) {
    const int r0 = ty * 4;
    const int ca = tx * 4, cb = 64 + tx * 4;
    #pragma unroll 4
    for (int k = 0; k < K; ++k) {
        float aa[4];
        #pragma unroll
        for (int i = 0; i < 4; ++i) aa[i] = A[(r0 + i) * K + k];
        float4 b0 = *reinterpret_cast<const float4*>(W + k * 128 + ca);
        float4 b1 = *reinterpret_cast<const float4*>(W + k * 128 + cb);
        float bb[8] = {b0.x, b0.y, b0.z, b0.w, b1.x, b1.y, b1.z, b1.w};
        #pragma unroll
        for (int i = 0; i < 4; ++i)
            #pragma unroll
            for (int j = 0; j < 8; ++j)
                acc[i][j] = fmaf(aa[i], bb[j], acc[i][j]);
    }
}

__device__ __forceinline__ void store_row4(float* base, int row, int tx, const float v[8]) {
    *reinterpret_cast<float4*>(base + row * 128 + tx * 4)      = make_float4(v[0], v[1], v[2], v[3]);
    *reinterpret_cast<float4*>(base + row * 128 + 64 + tx * 4) = make_float4(v[4], v[5], v[6], v[7]);
}

__device__ __forceinline__ unsigned smem_u32(const void* p) {
    unsigned a;
    asm("{ .reg .u64 t; cvta.to.shared.u64 t, %1; cvt.u32.u64 %0, t; }" : "=r"(a) : "l"(p));
    return a;
}

#define LDSM_X4(r, addr)                                                       \
    asm volatile("ldmatrix.sync.aligned.m8n8.x4.shared.b16 {%0,%1,%2,%3}, [%4];" \
        : "=r"((r)[0]), "=r"((r)[1]), "=r"((r)[2]), "=r"((r)[3]) : "r"(addr))

#define MMA16816(d, a, b0, b1)                                                 \
    asm volatile("mma.sync.aligned.m16n8k16.row.col.f32.f16.f16.f32 "          \
        "{%0,%1,%2,%3}, {%4,%5,%6,%7}, {%8,%9}, {%0,%1,%2,%3};"                \
        : "+f"((d)[0]), "+f"((d)[1]), "+f"((d)[2]), "+f"((d)[3])               \
        : "r"((a)[0]), "r"((a)[1]), "r"((a)[2]), "r"((a)[3]), "r"(b0), "r"(b1))

#define GBAR(gid)                                                              \
    asm volatile("bar.sync %0, %1;" :: "r"(gid), "r"(256u) : "memory")

#define CPA16(dst, src)                                                        \
    asm volatile("cp.async.cg.shared.global [%0], [%1], 16;"                   \
        :: "r"(dst), "l"(src) : "memory")
#define CPA_COMMIT() asm volatile("cp.async.commit_group;" ::: "memory")
#define CPA_WAIT()   asm volatile("cp.async.wait_group 0;" ::: "memory")

// =====================================================================
// Kernel kW: precompute Wv2^T and Wv3^T fp16 into padded [128][136].
// grid 128 x 256
// =====================================================================
__global__ __launch_bounds__(256) void kW(Params P) {
    int t = blockIdx.x * 256 + threadIdx.x;
    if (t < 16384) {
        int n = t >> 7, k = t & 127;
        g_Wh[n * 136 + k] = __half_as_ushort(__float2half_rn(P.p[14][k * 128 + n]));
    } else if (t < 32768) {
        int i = t - 16384;
        int n = i >> 7, k = i & 127;
        g_W3h[n * 136 + k] = __half_as_ushort(__float2half_rn(P.p[16][k * 128 + n]));
    }
}

// =====================================================================
// Kernel A1: keys / queries MLPs + hk, hq projections. grid (64 bc, 2 paths)
// =====================================================================
__global__ __launch_bounds__(256) void kA1(Params P) {
    extern __shared__ float sm[];
    float* X  = sm;
    float* W  = sm + 6144;
    float* T1 = W + 16384;
    float* T2 = T1 + 8192;
    const int t = threadIdx.x, tx = t & 15, ty = t >> 4;
    const int bc = blockIdx.x;
    const int r0 = ty * 4;
    float acc[4][8];

    if (blockIdx.y == 0) {
        cp4(X, P.p[0] + bc * 6144, 6144, t);
        cp4(W, P.p[2], 12288, t);
        __syncthreads();
        zero_acc8(acc);
        gemm_tile<96>(X, W, acc, tx, ty);
        {
            const float aK = P.p[18][0];
            const float* bk1 = P.p[3];
            #pragma unroll
            for (int i = 0; i < 4; ++i) {
                float v[8];
                #pragma unroll
                for (int j = 0; j < 8; ++j) {
                    int c = colidx(tx, j);
                    float x = acc[i][j] + bk1[c];
                    v[j] = x >= 0.f ? x : aK * x;
                }
                store_row4(T1, r0 + i, tx, v);
            }
        }
        __syncthreads();
        cp4(W, P.p[4], 16384, t);
        __syncthreads();
        zero_acc8(acc);
        gemm_tile<128>(T1, W, acc, tx, ty);
        {
            const float* bk2 = P.p[5];
            const float* gK  = P.p[20];
            const float* beK = P.p[21];
            #pragma unroll
            for (int i = 0; i < 4; ++i) {
                float v[8]; float s1 = 0.f, s2 = 0.f;
                #pragma unroll
                for (int j = 0; j < 8; ++j) {
                    int c = colidx(tx, j);
                    float x = tanha(acc[i][j] + bk2[c]);
                    v[j] = x; s1 += x; s2 += x * x;
                }
                #pragma unroll
                for (int off = 8; off >= 1; off >>= 1) {
                    s1 += __shfl_xor_sync(0xffffffffu, s1, off);
                    s2 += __shfl_xor_sync(0xffffffffu, s2, off);
                }
                float m  = s1 * (1.f / 128.f);
                float va = s2 * (1.f / 128.f) - m * m;
                float rs = rsqrtf(va + 1e-5f);
                #pragma unroll
                for (int j = 0; j < 8; ++j) {
                    int c = colidx(tx, j);
                    v[j] = (v[j] - m) * rs * gK[c] + beK[c];
                }
                store_row4(T2, r0 + i, tx, v);
            }
        }
        __syncthreads();
        cp4(W, P.p[6], 16384, t);
        __syncthreads();
        zero_acc8(acc);
        gemm_tile<128>(T2, W, acc, tx, ty);
        {
            const float* bk3 = P.p[7];
            float* kout = g_keys + bc * 8192;
            #pragma unroll
            for (int i = 0; i < 4; ++i) {
                float v[8];
                #pragma unroll
                for (int j = 0; j < 8; ++j) v[j] = acc[i][j] + bk3[colidx(tx, j)];
                store_row4(T1, r0 + i, tx, v);
                store_row4(kout, r0 + i, tx, v);
            }
        }
        __syncthreads();
        cp4(W, P.p[12] + 16384, 16384, t);
        __syncthreads();
        zero_acc8(acc);
        gemm_tile<128>(T1, W, acc, tx, ty);
        {
            const float* bv1 = P.p[13];   // fold bv1 into hk here
            float* hkout = g_hk + bc * 8192;
            #pragma unroll
            for (int i = 0; i < 4; ++i) {
                float v[8];
                #pragma unroll
                for (int j = 0; j < 8; ++j) v[j] = acc[i][j] + bv1[colidx(tx, j)];
                store_row4(hkout, r0 + i, tx, v);
            }
        }
    } else {
        cp4(X, P.p[1] + bc * 6144, 6144, t);
        cp4(W, P.p[8], 12288, t);
        __syncthreads();
        zero_acc8(acc);
        gemm_tile<96>(X, W, acc, tx, ty);
        {
            const float* bq1 = P.p[9];
            #pragma unroll
            for (int i = 0; i < 4; ++i) {
                float v[8];
                #pragma unroll
                for (int j = 0; j < 8; ++j) v[j] = tanha(acc[i][j] + bq1[colidx(tx, j)]);
                store_row4(T1, r0 + i, tx, v);
            }
        }
        __syncthreads();
        cp4(W, P.p[10], 16384, t);
        __syncthreads();
        zero_acc8(acc);
        gemm_tile<128>(T1, W, acc, tx, ty);
        {
            const float* bq2 = P.p[11];
            float* qout = g_queries + bc * 8192;
            #pragma unroll
            for (int i = 0; i < 4; ++i) {
                float v[8];
                #pragma unroll
                for (int j = 0; j < 8; ++j) v[j] = acc[i][j] + bq2[colidx(tx, j)];
                store_row4(T2, r0 + i, tx, v);
                store_row4(qout, r0 + i, tx, v);
            }
        }
        __syncthreads();
        cp4(W, P.p[12], 16384, t);
        __syncthreads();
        zero_acc8(acc);
        gemm_tile<128>(T2, W, acc, tx, ty);
        {
            float* hqout = g_hq + bc * 8192;
            #pragma unroll
            for (int i = 0; i < 4; ++i) {
                float v[8];
                #pragma unroll
                for (int j = 0; j < 8; ++j) v[j] = acc[i][j];
                store_row4(hqout, r0 + i, tx, v);
            }
        }
    }
}

// =====================================================================
// Kernel A2: logits + softmax over n (axis 2) + attn row sums. grid 64
// =====================================================================
__global__ __launch_bounds__(256) void kA2(Params P) {
    extern __shared__ float sm[];
    float* Kp = sm;
    float* Q  = sm + 8256;
    float* L  = Q + 8256;
    const int t = threadIdx.x, tx = t & 15, ty = t >> 4;
    const int bc = blockIdx.x;

    for (int i = t; i < 8192; i += NTHREADS) {
        int r = i >> 7, c = i & 127;
        Kp[r * 129 + c] = g_keys[bc * 8192 + i];
        Q [r * 129 + c] = g_queries[bc * 8192 + i];
    }
    __syncthreads();

    float acc[4][4];
    #pragma unroll
    for (int i = 0; i < 4; ++i)
        #pragma unroll
        for (int j = 0; j < 4; ++j) acc[i][j] = 0.f;
    #pragma unroll 4
    for (int k = 0; k < 128; ++k) {
        float a[4], b[4];
        #pragma unroll
        for (int i = 0; i < 4; ++i) a[i] = Kp[(ty * 4 + i) * 129 + k];
        #pragma unroll
        for (int j = 0; j < 4; ++j) b[j] = Q[(tx * 4 + j) * 129 + k];
        #pragma unroll
        for (int i = 0; i < 4; ++i)
            #pragma unroll
            for (int j = 0; j < 4; ++j) acc[i][j] = fmaf(a[i], b[j], acc[i][j]);
    }
    #pragma unroll
    for (int i = 0; i < 4; ++i)
        #pragma unroll
        for (int j = 0; j < 4; ++j) L[(ty * 4 + i) * 65 + tx * 4 + j] = acc[i][j];
    __syncthreads();

    if (t < 64) {
        int m = t;
        float mx = -1e30f;
        for (int n = 0; n < 64; ++n) mx = fmaxf(mx, L[n * 65 + m]);
        float s = 0.f;
        for (int n = 0; n < 64; ++n) { float e = expf(L[n * 65 + m] - mx); L[n * 65 + m] = e; s += e; }
        float inv = 1.f / s;
        for (int n = 0; n < 64; ++n) L[n * 65 + m] *= inv;
    }
    __syncthreads();
    if (t < 64) {
        int n = t; float s = 0.f;
        for (int m = 0; m < 64; ++m) {
            float v = L[n * 65 + m];
            g_attn[bc * 4096 + n * 64 + m] = v;
            s += v;
        }
        g_asum[bc * 64 + n] = s;
    }
}

// =====================================================================
// Kernel B (persistent, dual-group HMMA, fp16 single chain + cp.async
// prefetch of hq/hk): grid 148 x 512. 2 barriers/item.
// =====================================================================
// byte offsets within dynamic smem
#define KB_WH    0u                 // 34816 (fp16 W)
#define KB_A     34816u             // + group*34816 (Ahi only)
#define KB_STG   104448u            // + group*33792: hq(32768) hk(1024)
#define KB_CONST 172032u            // bv2s, gvs, bevs (128 floats each) + pad
#define KB_RED   174080u            // + group*4096 (8 warps x 128 floats)
#define KB_SMEM_BYTES 182272

__global__ __launch_bounds__(512, 1) void kB(Params P) {
    extern __shared__ char smc[];
    const int t = threadIdx.x;
    const int wid = t >> 5, l = t & 31;
    const int group = wid >> 3;         // 0 or 1
    const int gt = t & 255;             // thread within group
    const int gw = wid & 7;             // warp within group
    const int gid = group + 1;          // named barrier id

    float* bv2s = reinterpret_cast<float*>(smc + KB_CONST);
    float* gvs  = bv2s + 128;
    float* bevs = gvs + 128;
    float* red  = reinterpret_cast<float*>(smc + KB_RED + group * 4096u);
    float* stg  = reinterpret_cast<float*>(smc + KB_STG + group * 33792u);

    unsigned short* Ahi = reinterpret_cast<unsigned short*>(smc + KB_A + group * 34816u);

    // ---- one-time staging: W fp16 + const vectors (all 512 threads) ----
    {
        const float4* s0 = reinterpret_cast<const float4*>(g_Wh);
        float4* d0 = reinterpret_cast<float4*>(smc + KB_WH);
        for (int i = t; i < 2176; i += 512) d0[i] = s0[i];
        if (t < 128) {
            bv2s[t] = P.p[15][t];
            gvs[t]  = P.p[22][t];
            bevs[t] = P.p[23][t];
        }
    }

    const float aV = P.p[19][0];
    const unsigned sbase = smem_u32(smc);
    const unsigned stgAddr = sbase + KB_STG + group * 33792u;
    const unsigned aAddr = sbase + KB_A + group * 34816u
                         + ((gw * 16 + (l & 15)) * 136) * 2 + (l >> 4) * 16;
    const unsigned bRow = (l & 7) + ((l >> 4) & 1) * 8;
    const unsigned bAddr = sbase + KB_WH + (bRow * 136) * 2 + ((l >> 3) & 1) * 16;

    const int qr = l >> 2, qc = l & 3;
    const int item0 = blockIdx.x * 2 + group;

    // ---- prologue prefetch: first item's hq + hk into staging ----
    if (item0 < 2048) {
        int nbc = item0 >> 5, nn0 = (item0 & 31) * 2;
        const float* hsrc = g_hq + nbc * 8192;
        #pragma unroll
        for (int k2 = 0; k2 < 8; ++k2) {
            unsigned u = (unsigned)(k2 * 256 + gt);
            CPA16(stgAddr + u * 16, hsrc + u * 4);
        }
        if (gt < 64)
            CPA16(stgAddr + 32768 + gt * 16, g_hk + (nbc * 64 + nn0) * 128 + gt * 4);
    }
    CPA_COMMIT();
    CPA_WAIT();
    __syncthreads();

    for (int item = item0; item < 2048; item += 296) {
        const int bc = item >> 5;
        const int n0 = (item & 31) * 2;

        // ---- build A tile (rows = n_l*64+m, cols = k), fp16, from staging ----
        {
            const int r = gt >> 1, ac = gt & 1;
            const int m = r & 63, nl = r >> 6;
            const float* hq = stg + m * 128 + ac * 64;
            const float* hk = stg + 8192 + nl * 128 + ac * 64;   // hk already has bv1 folded
            unsigned short* ph = Ahi + r * 136 + ac * 64;
            #pragma unroll 4
            for (int j = 0; j < 16; ++j) {
                float4 h  = *reinterpret_cast<const float4*>(hq + j * 4);
                float4 kk = *reinterpret_cast<const float4*>(hk + j * 4);
                float a0 = h.x + kk.x; a0 = a0 >= 0.f ? a0 : aV * a0;
                float a1 = h.y + kk.y; a1 = a1 >= 0.f ? a1 : aV * a1;
                float a2 = h.z + kk.z; a2 = a2 >= 0.f ? a2 : aV * a2;
                float a3 = h.w + kk.w; a3 = a3 >= 0.f ? a3 : aV * a3;
                __half2 h01 = __floats2half2_rn(a0, a1);
                __half2 h23 = __floats2half2_rn(a2, a3);
                uint2 vh;
                vh.x = *reinterpret_cast<unsigned*>(&h01);
                vh.y = *reinterpret_cast<unsigned*>(&h23);
                *reinterpret_cast<uint2*>(ph + j * 4) = vh;
            }
        }
        GBAR(gid);

        // ---- issue prefetch for NEXT item (lands during mainloop) ----
        {
            int nitem = item + 296;
            if (nitem < 2048) {
                int nbc = nitem >> 5, nn0 = (nitem & 31) * 2;
                const float* hsrc = g_hq + nbc * 8192;
                #pragma unroll
                for (int k2 = 0; k2 < 8; ++k2) {
                    unsigned u = (unsigned)(k2 * 256 + gt);
                    CPA16(stgAddr + u * 16, hsrc + u * 4);
                }
                if (gt < 64)
                    CPA16(stgAddr + 32768 + gt * 16, g_hk + (nbc * 64 + nn0) * 128 + gt * 4);
            }
            CPA_COMMIT();
        }

        // ---- GEMM: 8 warps x (16m x 128n), K=128, single fp16 chain ----
        float acc[16][4];
        #pragma unroll
        for (int nt = 0; nt < 16; ++nt)
            #pragma unroll
            for (int j = 0; j < 4; ++j) acc[nt][j] = 0.f;

        #pragma unroll
        for (int ks = 0; ks < 8; ++ks) {
            unsigned ah[4];
            LDSM_X4(ah, aAddr + ks * 32);
            #pragma unroll
            for (int p = 0; p < 8; ++p) {
                unsigned bh[4];
                LDSM_X4(bh, bAddr + p * 4352 + ks * 32);
                MMA16816(acc[2*p],     ah, bh[0], bh[1]);
                MMA16816(acc[2*p + 1], ah, bh[2], bh[3]);
            }
        }

        // ---- epilogue: tanh.approx + folded LN + attn weighting ----
        {
            float s1a = 0.f, s2a = 0.f, s1b = 0.f, s2b = 0.f;
            #pragma unroll
            for (int nt = 0; nt < 16; ++nt) {
                int c0 = nt * 8 + qc * 2;
                float x0 = tanha(acc[nt][0] + bv2s[c0]);
                float x1 = tanha(acc[nt][1] + bv2s[c0 + 1]);
                float x2 = tanha(acc[nt][2] + bv2s[c0]);
                float x3 = tanha(acc[nt][3] + bv2s[c0 + 1]);
                acc[nt][0] = x0; acc[nt][1] = x1; acc[nt][2] = x2; acc[nt][3] = x3;
                s1a += x0 + x1; s2a += x0 * x0 + x1 * x1;
                s1b += x2 + x3; s2b += x2 * x2 + x3 * x3;
            }
            #pragma unroll
            for (int off = 1; off <= 2; off <<= 1) {
                s1a += __shfl_xor_sync(0xffffffffu, s1a, off);
                s2a += __shfl_xor_sync(0xffffffffu, s2a, off);
                s1b += __shfl_xor_sync(0xffffffffu, s1b, off);
                s2b += __shfl_xor_sync(0xffffffffu, s2b, off);
            }
            float mua = s1a * (1.f / 128.f);
            float rsa = rsqrtf(s2a * (1.f / 128.f) - mua * mua + 1e-5f);
            float mub = s1b * (1.f / 128.f);
            float rsb = rsqrtf(s2b * (1.f / 128.f) - mub * mub + 1e-5f);

            const int nn = n0 + (gw >> 2);
            const int m0 = (gw & 3) * 16 + qr;
            const float* ab = g_attn + bc * 4096 + nn * 64;
            float wa = ab[m0], wb = ab[m0 + 8];

            float aco0 = wa * rsa, aco1 = wb * rsb;
            float bsum = fmaf(aco0, mua, aco1 * mub);
            float ws = wa + wb;

            float part[32];
            #pragma unroll
            for (int nt = 0; nt < 16; ++nt) {
                #pragma unroll
                for (int jj = 0; jj < 2; ++jj) {
                    int c = nt * 8 + qc * 2 + jj;
                    float inner = fmaf(aco0, acc[nt][jj],
                                  fmaf(aco1, acc[nt][jj + 2], -bsum));
                    part[nt * 2 + jj] = fmaf(gvs[c], inner, bevs[c] * ws);
                }
            }
            #pragma unroll
            for (int off = 4; off <= 16; off <<= 1)
                #pragma unroll
                for (int s = 0; s < 32; ++s)
                    part[s] += __shfl_xor_sync(0xffffffffu, part[s], off);
            if (l < 4) {
                #pragma unroll
                for (int nt = 0; nt < 16; ++nt) {
                    red[gw * 128 + nt * 8 + l * 2 + 0] = part[nt * 2 + 0];
                    red[gw * 128 + nt * 8 + l * 2 + 1] = part[nt * 2 + 1];
                }
            }
        }
        CPA_WAIT();
        GBAR(gid);

        // ---- final: combine 4 m-warps per n, store g_G ----
        {
            const int nl = gt >> 7, c = gt & 127;
            const float* rb = red + nl * 512 + c;
            g_G[(bc * 64 + n0 + nl) * 128 + c] = rb[0] + rb[128] + rb[256] + rb[384];
        }
    }
}

// =====================================================================
// Kernel C (HMMA): out = G @ Wv3 + asum * bv3. grid 32, one CTA = 2 bc
// (128 rows x 128 cols x K=128, single fp16 chain).
// =====================================================================
// smem layout (bytes): union region [0, 67584):
//   phase 1: W3 fp16 [0, 34816), G fp16 [34816, 69632)  -- G tail > union ok, see below
//   phase 2: result fp32 pitch 132 [0, 67584)
// asum (128 f) + bv3 (128 f) at 69632
#define KC_W3   0u
#define KC_G    34816u
#define KC_MISC 69632u
#define KC_SMEM_BYTES (69632 + 1024)

__global__ __launch_bounds__(256, 1) void kC(Params P, float* __restrict__ out) {
    extern __shared__ char smc[];
    const int t = threadIdx.x;
    const int gw = t >> 5, l = t & 31;
    const int bc0 = blockIdx.x * 2;

    float* asum_s = reinterpret_cast<float*>(smc + KC_MISC);
    float* bv3_s  = asum_s + 128;
    unsigned short* Gt = reinterpret_cast<unsigned short*>(smc + KC_G);
    float* res = reinterpret_cast<float*>(smc);   // phase 2, pitch 132

    // ---- stage W3 fp16 + asum + bv3 ----
    {
        const float4* s0 = reinterpret_cast<const float4*>(g_W3h);
        float4* d0 = reinterpret_cast<float4*>(smc + KC_W3);
        for (int i = t; i < 2176; i += 256) d0[i] = s0[i];
        if (t < 128) {
            asum_s[t] = g_asum[bc0 * 64 + t];
            bv3_s[t]  = P.p[17][t];
        }
    }

    // ---- build G tile fp16 (rows 0..127 over 2 bc) ----
    {
        const int r = t >> 1, ac = t & 1;
        const float* src = g_G + bc0 * 8192 + r * 128 + ac * 64;
        unsigned short* ph = Gt + r * 136 + ac * 64;
        #pragma unroll 4
        for (int j = 0; j < 16; ++j) {
            float4 v = *reinterpret_cast<const float4*>(src + j * 4);
            __half2 h01 = __floats2half2_rn(v.x, v.y);
            __half2 h23 = __floats2half2_rn(v.z, v.w);
            uint2 vh;
            vh.x = *reinterpret_cast<unsigned*>(&h01);
            vh.y = *reinterpret_cast<unsigned*>(&h23);
            *reinterpret_cast<uint2*>(ph + j * 4) = vh;
        }
    }
    __syncthreads();

    // ---- GEMM: 8 warps x (16 rows x 128 cols), K=128, single fp16 chain ----
    const unsigned sbase = smem_u32(smc);
    const unsigned aAddr = sbase + KC_G + ((gw * 16 + (l & 15)) * 136) * 2 + (l >> 4) * 16;
    const unsigned bRow = (l & 7) + ((l >> 4) & 1) * 8;
    const unsigned bAddr = sbase + KC_W3 + (bRow * 136) * 2 + ((l >> 3) & 1) * 16;

    float acc[16][4];
    #pragma unroll
    for (int nt = 0; nt < 16; ++nt)
        #pragma unroll
        for (int j = 0; j < 4; ++j) acc[nt][j] = 0.f;

    #pragma unroll
    for (int ks = 0; ks < 8; ++ks) {
        unsigned ah[4];
        LDSM_X4(ah, aAddr + ks * 32);
        #pragma unroll
        for (int p = 0; p < 8; ++p) {
            unsigned bh[4];
            LDSM_X4(bh, bAddr + p * 4352 + ks * 32);
            MMA16816(acc[2*p],     ah, bh[0], bh[1]);
            MMA16816(acc[2*p + 1], ah, bh[2], bh[3]);
        }
    }
    __syncthreads();   // all warps done reading W3/G before overwrite

    // ---- stage results to smem (pitch 132), then coalesced store ----
    {
        const int qr = l >> 2, qc = l & 3;
        const int r0 = gw * 16 + qr, r1 = r0 + 8;
        #pragma unroll
        for (int nt = 0; nt < 16; ++nt) {
            #pragma unroll
            for (int jj = 0; jj < 2; ++jj) {
                int c = nt * 8 + qc * 2 + jj;
                res[r0 * 132 + c] = acc[nt][jj];
                res[r1 * 132 + c] = acc[nt][jj + 2];
            }
        }
    }
    __syncthreads();

    {
        float* ob = out + bc0 * 8192;
        #pragma unroll
        for (int k2 = 0; k2 < 16; ++k2) {
            int idx = k2 * 1024 + t * 4;
            int row = idx >> 7, col = idx & 127;
            float4 v = *reinterpret_cast<const float4*>(res + row * 132 + col);
            float as = asum_s[row];
            v.x = fmaf(as, bv3_s[col + 0], v.x);
            v.y = fmaf(as, bv3_s[col + 1], v.y);
            v.z = fmaf(as, bv3_s[col + 2], v.z);
            v.w = fmaf(as, bv3_s[col + 3], v.w);
            *reinterpret_cast<float4*>(ob + idx) = v;
        }
    }
}

// =====================================================================
extern "C" void kernel_launch(void* const* d_in, const int* in_sizes, int n_in,
                              void* d_out, int out_size) {
    (void)in_sizes; (void)n_in; (void)out_size;
    Params P;
    for (int i = 0; i < 24; ++i) P.p[i] = reinterpret_cast<const float*>(d_in[i]);

    const int SMEM_A1 = (6144 + 16384 + 8192 + 8192) * 4;
    const int SMEM_A2 = (8256 + 8256 + 64 * 65) * 4;
    const int SMEM_B  = KB_SMEM_BYTES;
    const int SMEM_C  = KC_SMEM_BYTES;

    cudaFuncSetAttribute(kA1, cudaFuncAttributeMaxDynamicSharedMemorySize, SMEM_A1);
    cudaFuncSetAttribute(kA2, cudaFuncAttributeMaxDynamicSharedMemorySize, SMEM_A2);
    cudaFuncSetAttribute(kB,  cudaFuncAttributeMaxDynamicSharedMemorySize, SMEM_B);
    cudaFuncSetAttribute(kC,  cudaFuncAttributeMaxDynamicSharedMemorySize, SMEM_C);

    kW <<<128, 256>>>(P);
    kA1<<<dim3(64, 2), NTHREADS, SMEM_A1>>>(P);
    kA2<<<64, NTHREADS, SMEM_A2>>>(P);
    kB <<<148, 512, SMEM_B>>>(P);
    kC <<<32, 256, SMEM_C>>>(P, reinterpret_cast<float*>(d_out));
}

// round 15
// speedup vs baseline: 1.3290x; 1.0808x over previous
#include <cuda_runtime.h>
#include <cuda_bf16.h>
#include <cuda_fp16.h>

#define NTHREADS 256

struct Params { const float* p[24]; };

// ---- scratch (static device globals; no allocation) ----
__device__ float g_keys   [64*64*128];
__device__ float g_queries[64*64*128];
__device__ float g_hk     [64*64*128];   // hk + bv1 folded
__device__ float g_hq     [64*64*128];
__device__ float g_attn   [64*64*64];
__device__ float g_asum   [64*64];
__device__ float g_G      [64*64*128];
__device__ int   g_ready  [64];
// Wv2^T / Wv3^T as [n][k], fp16, rows padded to 136 elems (272B)
__device__ __align__(16) unsigned short g_Wh [128*136];
__device__ __align__(16) unsigned short g_W3h[128*136];

__device__ __forceinline__ float tanha(float x) {
    float y;
    asm("tanh.approx.f32 %0, %1;" : "=f"(y) : "f"(x));
    return y;
}

__device__ __forceinline__ int colidx(int tx, int j) { return j < 4 ? tx*4 + j : 60 + tx*4 + j; }

__device__ __forceinline__ void zero_acc8(float acc[4][8]) {
    #pragma unroll
    for (int i = 0; i < 4; ++i)
        #pragma unroll
        for (int j = 0; j < 8; ++j) acc[i][j] = 0.f;
}

template<int K>
__device__ __forceinline__ void gemm_tile(const float* __restrict__ A, const float* __restrict__ W,
                                          float acc[4][8], int tx, int ty) {
    const int r0 = ty * 4;
    const int ca = tx * 4, cb = 64 + tx * 4;
    #pragma unroll 4
    for (int k = 0; k < K; ++k) {
        float aa[4];
        #pragma unroll
        for (int i = 0; i < 4; ++i) aa[i] = A[(r0 + i) * K + k];
        float4 b0 = *reinterpret_cast<const float4*>(W + k * 128 + ca);
        float4 b1 = *reinterpret_cast<const float4*>(W + k * 128 + cb);
        float bb[8] = {b0.x, b0.y, b0.z, b0.w, b1.x, b1.y, b1.z, b1.w};
        #pragma unroll
        for (int i = 0; i < 4; ++i)
            #pragma unroll
            for (int j = 0; j < 8; ++j)
                acc[i][j] = fmaf(aa[i], bb[j], acc[i][j]);
    }
}

__device__ __forceinline__ void store_row4(float* base, int row, int tx, const float v[8]) {
    *reinterpret_cast<float4*>(base + row * 128 + tx * 4)      = make_float4(v[0], v[1], v[2], v[3]);
    *reinterpret_cast<float4*>(base + row * 128 + 64 + tx * 4) = make_float4(v[4], v[5], v[6], v[7]);
}

__device__ __forceinline__ unsigned smem_u32(const void* p) {
    unsigned a;
    asm("{ .reg .u64 t; cvta.to.shared.u64 t, %1; cvt.u32.u64 %0, t; }" : "=r"(a) : "l"(p));
    return a;
}

#define LDSM_X4(r, addr)                                                       \
    asm volatile("ldmatrix.sync.aligned.m8n8.x4.shared.b16 {%0,%1,%2,%3}, [%4];" \
        : "=r"((r)[0]), "=r"((r)[1]), "=r"((r)[2]), "=r"((r)[3]) : "r"(addr))

#define MMA16816(d, a, b0, b1)                                                 \
    asm volatile("mma.sync.aligned.m16n8k16.row.col.f32.f16.f16.f32 "          \
        "{%0,%1,%2,%3}, {%4,%5,%6,%7}, {%8,%9}, {%0,%1,%2,%3};"                \
        : "+f"((d)[0]), "+f"((d)[1]), "+f"((d)[2]), "+f"((d)[3])               \
        : "r"((a)[0]), "r"((a)[1]), "r"((a)[2]), "r"((a)[3]), "r"(b0), "r"(b1))

#define GBAR(gid)                                                              \
    asm volatile("bar.sync %0, %1;" :: "r"(gid), "r"(256u) : "memory")

#define CPA16(dst, src)                                                        \
    asm volatile("cp.async.cg.shared.global [%0], [%1], 16;"                   \
        :: "r"(dst), "l"(src) : "memory")
#define CPA_COMMIT() asm volatile("cp.async.commit_group;" ::: "memory")
#define CPA_WAIT()   asm volatile("cp.async.wait_group 0;" ::: "memory")

__device__ __forceinline__ void stage_async(unsigned dst, const float* src, int nfl, int t) {
    for (int i = t * 4; i < nfl; i += NTHREADS * 4)
        CPA16(dst + (unsigned)i * 4u, src + i);
}

// =====================================================================
// Kernel A1: keys / queries MLPs with double-buffered cp.async W
// prefetch. grid (64, 3): y=0 keys, y=1 queries, y=2 weight-convert+reset
// =====================================================================
// smem float offsets: X 0(6144) W0 6144(16384) W1 22528(16384) T1 38912(8192) T2 47104(8192)
#define KA1_SMEM_FLOATS 55296

__global__ __launch_bounds__(256) void kA1(Params P) {
    // ---- y==2: convert Wv2^T / Wv3^T to fp16 + reset ready flags ----
    if (blockIdx.y == 2) {
        int idx = blockIdx.x * 256 + threadIdx.x;   // 0..16383
        int n = idx >> 7, k = idx & 127;
        g_Wh [n * 136 + k] = __half_as_ushort(__float2half_rn(P.p[14][k * 128 + n]));
        g_W3h[n * 136 + k] = __half_as_ushort(__float2half_rn(P.p[16][k * 128 + n]));
        if (blockIdx.x == 0 && threadIdx.x < 64) g_ready[threadIdx.x] = 0;
        return;
    }

    extern __shared__ float sm[];
    float* X  = sm;
    float* W0 = sm + 6144;
    float* W1 = sm + 22528;
    float* T1 = sm + 38912;
    float* T2 = sm + 47104;
    const int t = threadIdx.x, tx = t & 15, ty = t >> 4;
    const int bc = blockIdx.x;
    const int r0 = ty * 4;
    const unsigned sb = smem_u32(sm);
    const unsigned uX = sb, uW0 = sb + 6144u * 4u, uW1 = sb + 22528u * 4u;
    float acc[4][8];

    if (blockIdx.y == 0) {
        // -------- keys path --------
        stage_async(uX, P.p[0] + bc * 6144, 6144, t);
        stage_async(uW0, P.p[2], 12288, t);
        CPA_COMMIT(); CPA_WAIT(); __syncthreads();

        stage_async(uW1, P.p[4], 16384, t); CPA_COMMIT();
        zero_acc8(acc);
        gemm_tile<96>(X, W0, acc, tx, ty);
        {
            const float aK = P.p[18][0];
            const float* bk1 = P.p[3];
            #pragma unroll
            for (int i = 0; i < 4; ++i) {
                float v[8];
                #pragma unroll
                for (int j = 0; j < 8; ++j) {
                    int c = colidx(tx, j);
                    float x = acc[i][j] + bk1[c];
                    v[j] = x >= 0.f ? x : aK * x;
                }
                store_row4(T1, r0 + i, tx, v);
            }
        }
        CPA_WAIT(); __syncthreads();

        stage_async(uW0, P.p[6], 16384, t); CPA_COMMIT();
        zero_acc8(acc);
        gemm_tile<128>(T1, W1, acc, tx, ty);
        {
            const float* bk2 = P.p[5];
            const float* gK  = P.p[20];
            const float* beK = P.p[21];
            #pragma unroll
            for (int i = 0; i < 4; ++i) {
                float v[8]; float s1 = 0.f, s2 = 0.f;
                #pragma unroll
                for (int j = 0; j < 8; ++j) {
                    int c = colidx(tx, j);
                    float x = tanha(acc[i][j] + bk2[c]);
                    v[j] = x; s1 += x; s2 += x * x;
                }
                #pragma unroll
                for (int off = 8; off >= 1; off >>= 1) {
                    s1 += __shfl_xor_sync(0xffffffffu, s1, off);
                    s2 += __shfl_xor_sync(0xffffffffu, s2, off);
                }
                float m  = s1 * (1.f / 128.f);
                float va = s2 * (1.f / 128.f) - m * m;
                float rs = rsqrtf(va + 1e-5f);
                #pragma unroll
                for (int j = 0; j < 8; ++j) {
                    int c = colidx(tx, j);
                    v[j] = (v[j] - m) * rs * gK[c] + beK[c];
                }
                store_row4(T2, r0 + i, tx, v);
            }
        }
        CPA_WAIT(); __syncthreads();

        stage_async(uW1, P.p[12] + 16384, 16384, t); CPA_COMMIT();
        zero_acc8(acc);
        gemm_tile<128>(T2, W0, acc, tx, ty);
        {
            const float* bk3 = P.p[7];
            float* kout = g_keys + bc * 8192;
            #pragma unroll
            for (int i = 0; i < 4; ++i) {
                float v[8];
                #pragma unroll
                for (int j = 0; j < 8; ++j) v[j] = acc[i][j] + bk3[colidx(tx, j)];
                store_row4(T1, r0 + i, tx, v);
                store_row4(kout, r0 + i, tx, v);
            }
        }
        CPA_WAIT(); __syncthreads();

        zero_acc8(acc);
        gemm_tile<128>(T1, W1, acc, tx, ty);
        {
            const float* bv1 = P.p[13];
            float* hkout = g_hk + bc * 8192;
            #pragma unroll
            for (int i = 0; i < 4; ++i) {
                float v[8];
                #pragma unroll
                for (int j = 0; j < 8; ++j) v[j] = acc[i][j] + bv1[colidx(tx, j)];
                store_row4(hkout, r0 + i, tx, v);
            }
        }
    } else {
        // -------- queries path --------
        stage_async(uX, P.p[1] + bc * 6144, 6144, t);
        stage_async(uW0, P.p[8], 12288, t);
        CPA_COMMIT(); CPA_WAIT(); __syncthreads();

        stage_async(uW1, P.p[10], 16384, t); CPA_COMMIT();
        zero_acc8(acc);
        gemm_tile<96>(X, W0, acc, tx, ty);
        {
            const float* bq1 = P.p[9];
            #pragma unroll
            for (int i = 0; i < 4; ++i) {
                float v[8];
                #pragma unroll
                for (int j = 0; j < 8; ++j) v[j] = tanha(acc[i][j] + bq1[colidx(tx, j)]);
                store_row4(T1, r0 + i, tx, v);
            }
        }
        CPA_WAIT(); __syncthreads();

        stage_async(uW0, P.p[12], 16384, t); CPA_COMMIT();
        zero_acc8(acc);
        gemm_tile<128>(T1, W1, acc, tx, ty);
        {
            const float* bq2 = P.p[11];
            float* qout = g_queries + bc * 8192;
            #pragma unroll
            for (int i = 0; i < 4; ++i) {
                float v[8];
                #pragma unroll
                for (int j = 0; j < 8; ++j) v[j] = acc[i][j] + bq2[colidx(tx, j)];
                store_row4(T2, r0 + i, tx, v);
                store_row4(qout, r0 + i, tx, v);
            }
        }
        CPA_WAIT(); __syncthreads();

        zero_acc8(acc);
        gemm_tile<128>(T2, W0, acc, tx, ty);
        {
            float* hqout = g_hq + bc * 8192;
            #pragma unroll
            for (int i = 0; i < 4; ++i) {
                float v[8];
                #pragma unroll
                for (int j = 0; j < 8; ++j) v[j] = acc[i][j];
                store_row4(hqout, r0 + i, tx, v);
            }
        }
    }
}

// =====================================================================
// Kernel B (persistent, dual-group HMMA, fp16 single chain, cp.async
// prefetch, INLINED kA2 with ready flags): grid 148 x 512.
// =====================================================================
#define KB_WH    0u                 // 34816 (fp16 W)
#define KB_A     34816u             // + group*34816 (Ahi only)
#define KB_STG   104448u            // + group*33792: hq(32768) hk(1024)
#define KB_CONST 172032u            // bv2s, gvs, bevs
#define KB_RED   174080u            // + group*4096
#define KB_SMEM_BYTES 182272

__global__ __launch_bounds__(512, 1) void kB(Params P) {
    extern __shared__ char smc[];
    const int t = threadIdx.x;
    const int wid = t >> 5, l = t & 31;
    const int group = wid >> 3;
    const int gt = t & 255;
    const int gw = wid & 7;
    const int gid = group + 1;

    // ---- inlined kA2: CTAs 0..63 compute softmax/attn for bc=blockIdx ----
    if (blockIdx.x < 64) {
        float* Kp = reinterpret_cast<float*>(smc);          // 64 x 129
        float* Q  = Kp + 8256;                              // 64 x 129
        float* L  = Q + 8256;                               // 64 x 65
        const int bcA = blockIdx.x;
        for (int i = t; i < 8192; i += 512) {
            int r = i >> 7, c = i & 127;
            Kp[r * 129 + c] = g_keys[bcA * 8192 + i];
            Q [r * 129 + c] = g_queries[bcA * 8192 + i];
        }
        __syncthreads();
        if (t < 256) {
            const int tx = t & 15, ty = t >> 4;
            float a2[4][4];
            #pragma unroll
            for (int i = 0; i < 4; ++i)
                #pragma unroll
                for (int j = 0; j < 4; ++j) a2[i][j] = 0.f;
            #pragma unroll 4
            for (int k = 0; k < 128; ++k) {
                float a[4], b[4];
                #pragma unroll
                for (int i = 0; i < 4; ++i) a[i] = Kp[(ty * 4 + i) * 129 + k];
                #pragma unroll
                for (int j = 0; j < 4; ++j) b[j] = Q[(tx * 4 + j) * 129 + k];
                #pragma unroll
                for (int i = 0; i < 4; ++i)
                    #pragma unroll
                    for (int j = 0; j < 4; ++j) a2[i][j] = fmaf(a[i], b[j], a2[i][j]);
            }
            #pragma unroll
            for (int i = 0; i < 4; ++i)
                #pragma unroll
                for (int j = 0; j < 4; ++j) L[(ty * 4 + i) * 65 + tx * 4 + j] = a2[i][j];
        }
        __syncthreads();
        if (t < 64) {
            int m = t;
            float mx = -1e30f;
            for (int n = 0; n < 64; ++n) mx = fmaxf(mx, L[n * 65 + m]);
            float s = 0.f;
            for (int n = 0; n < 64; ++n) { float e = expf(L[n * 65 + m] - mx); L[n * 65 + m] = e; s += e; }
            float inv = 1.f / s;
            for (int n = 0; n < 64; ++n) L[n * 65 + m] *= inv;
        }
        __syncthreads();
        if (t < 64) {
            int n = t; float s = 0.f;
            for (int m = 0; m < 64; ++m) {
                float v = L[n * 65 + m];
                g_attn[bcA * 4096 + n * 64 + m] = v;
                s += v;
            }
            g_asum[bcA * 64 + n] = s;
        }
        __threadfence();
        __syncthreads();
        if (t == 0) atomicExch(&g_ready[bcA], 1);
        __syncthreads();
    }

    float* bv2s = reinterpret_cast<float*>(smc + KB_CONST);
    float* gvs  = bv2s + 128;
    float* bevs = gvs + 128;
    float* red  = reinterpret_cast<float*>(smc + KB_RED + group * 4096u);
    float* stg  = reinterpret_cast<float*>(smc + KB_STG + group * 33792u);
    unsigned short* Ahi = reinterpret_cast<unsigned short*>(smc + KB_A + group * 34816u);

    // ---- one-time staging: W fp16 + const vectors ----
    {
        const float4* s0 = reinterpret_cast<const float4*>(g_Wh);
        float4* d0 = reinterpret_cast<float4*>(smc + KB_WH);
        for (int i = t; i < 2176; i += 512) d0[i] = s0[i];
        if (t < 128) {
            bv2s[t] = P.p[15][t];
            gvs[t]  = P.p[22][t];
            bevs[t] = P.p[23][t];
        }
    }

    const float aV = P.p[19][0];
    const unsigned sbase = smem_u32(smc);
    const unsigned stgAddr = sbase + KB_STG + group * 33792u;
    const unsigned aAddr = sbase + KB_A + group * 34816u
                         + ((gw * 16 + (l & 15)) * 136) * 2 + (l >> 4) * 16;
    const unsigned bRow = (l & 7) + ((l >> 4) & 1) * 8;
    const unsigned bAddr = sbase + KB_WH + (bRow * 136) * 2 + ((l >> 3) & 1) * 16;

    const int qr = l >> 2, qc = l & 3;
    const int item0 = blockIdx.x * 2 + group;

    // ---- prologue prefetch ----
    if (item0 < 2048) {
        int nbc = item0 >> 5, nn0 = (item0 & 31) * 2;
        const float* hsrc = g_hq + nbc * 8192;
        #pragma unroll
        for (int k2 = 0; k2 < 8; ++k2) {
            unsigned u = (unsigned)(k2 * 256 + gt);
            CPA16(stgAddr + u * 16, hsrc + u * 4);
        }
        if (gt < 64)
            CPA16(stgAddr + 32768 + gt * 16, g_hk + (nbc * 64 + nn0) * 128 + gt * 4);
    }
    CPA_COMMIT();
    CPA_WAIT();
    __syncthreads();

    for (int item = item0; item < 2048; item += 296) {
        const int bc = item >> 5;
        const int n0 = (item & 31) * 2;

        // wait until this bc's attn is published (usually already set)
        if (gt == 0) {
            while (atomicAdd(&g_ready[bc], 0) == 0) { }
        }

        // ---- build A tile fp16 from staging ----
        {
            const int r = gt >> 1, ac = gt & 1;
            const int m = r & 63, nl = r >> 6;
            const float* hq = stg + m * 128 + ac * 64;
            const float* hk = stg + 8192 + nl * 128 + ac * 64;
            unsigned short* ph = Ahi + r * 136 + ac * 64;
            #pragma unroll 4
            for (int j = 0; j < 16; ++j) {
                float4 h  = *reinterpret_cast<const float4*>(hq + j * 4);
                float4 kk = *reinterpret_cast<const float4*>(hk + j * 4);
                float a0 = h.x + kk.x; a0 = a0 >= 0.f ? a0 : aV * a0;
                float a1 = h.y + kk.y; a1 = a1 >= 0.f ? a1 : aV * a1;
                float a2 = h.z + kk.z; a2 = a2 >= 0.f ? a2 : aV * a2;
                float a3 = h.w + kk.w; a3 = a3 >= 0.f ? a3 : aV * a3;
                __half2 h01 = __floats2half2_rn(a0, a1);
                __half2 h23 = __floats2half2_rn(a2, a3);
                uint2 vh;
                vh.x = *reinterpret_cast<unsigned*>(&h01);
                vh.y = *reinterpret_cast<unsigned*>(&h23);
                *reinterpret_cast<uint2*>(ph + j * 4) = vh;
            }
        }
        GBAR(gid);

        // ---- prefetch next item ----
        {
            int nitem = item + 296;
            if (nitem < 2048) {
                int nbc = nitem >> 5, nn0 = (nitem & 31) * 2;
                const float* hsrc = g_hq + nbc * 8192;
                #pragma unroll
                for (int k2 = 0; k2 < 8; ++k2) {
                    unsigned u = (unsigned)(k2 * 256 + gt);
                    CPA16(stgAddr + u * 16, hsrc + u * 4);
                }
                if (gt < 64)
                    CPA16(stgAddr + 32768 + gt * 16, g_hk + (nbc * 64 + nn0) * 128 + gt * 4);
            }
            CPA_COMMIT();
        }

        // ---- GEMM: 8 warps x (16m x 128n), K=128, single fp16 chain ----
        float acc[16][4];
        #pragma unroll
        for (int nt = 0; nt < 16; ++nt)
            #pragma unroll
            for (int j = 0; j < 4; ++j) acc[nt][j] = 0.f;

        #pragma unroll
        for (int ks = 0; ks < 8; ++ks) {
            unsigned ah[4];
            LDSM_X4(ah, aAddr + ks * 32);
            #pragma unroll
            for (int p = 0; p < 8; ++p) {
                unsigned bh[4];
                LDSM_X4(bh, bAddr + p * 4352 + ks * 32);
                MMA16816(acc[2*p],     ah, bh[0], bh[1]);
                MMA16816(acc[2*p + 1], ah, bh[2], bh[3]);
            }
        }

        // ---- epilogue: tanh.approx + folded LN + attn weighting ----
        {
            float s1a = 0.f, s2a = 0.f, s1b = 0.f, s2b = 0.f;
            #pragma unroll
            for (int nt = 0; nt < 16; ++nt) {
                int c0 = nt * 8 + qc * 2;
                float x0 = tanha(acc[nt][0] + bv2s[c0]);
                float x1 = tanha(acc[nt][1] + bv2s[c0 + 1]);
                float x2 = tanha(acc[nt][2] + bv2s[c0]);
                float x3 = tanha(acc[nt][3] + bv2s[c0 + 1]);
                acc[nt][0] = x0; acc[nt][1] = x1; acc[nt][2] = x2; acc[nt][3] = x3;
                s1a += x0 + x1; s2a += x0 * x0 + x1 * x1;
                s1b += x2 + x3; s2b += x2 * x2 + x3 * x3;
            }
            #pragma unroll
            for (int off = 1; off <= 2; off <<= 1) {
                s1a += __shfl_xor_sync(0xffffffffu, s1a, off);
                s2a += __shfl_xor_sync(0xffffffffu, s2a, off);
                s1b += __shfl_xor_sync(0xffffffffu, s1b, off);
                s2b += __shfl_xor_sync(0xffffffffu, s2b, off);
            }
            float mua = s1a * (1.f / 128.f);
            float rsa = rsqrtf(s2a * (1.f / 128.f) - mua * mua + 1e-5f);
            float mub = s1b * (1.f / 128.f);
            float rsb = rsqrtf(s2b * (1.f / 128.f) - mub * mub + 1e-5f);

            const int nn = n0 + (gw >> 2);
            const int m0 = (gw & 3) * 16 + qr;
            const float* ab = g_attn + bc * 4096 + nn * 64;
            float wa = __ldcg(ab + m0), wb = __ldcg(ab + m0 + 8);

            float aco0 = wa * rsa, aco1 = wb * rsb;
            float bsum = fmaf(aco0, mua, aco1 * mub);
            float ws = wa + wb;

            float part[32];
            #pragma unroll
            for (int nt = 0; nt < 16; ++nt) {
                #pragma unroll
                for (int jj = 0; jj < 2; ++jj) {
                    int c = nt * 8 + qc * 2 + jj;
                    float inner = fmaf(aco0, acc[nt][jj],
                                  fmaf(aco1, acc[nt][jj + 2], -bsum));
                    part[nt * 2 + jj] = fmaf(gvs[c], inner, bevs[c] * ws);
                }
            }
            #pragma unroll
            for (int off = 4; off <= 16; off <<= 1)
                #pragma unroll
                for (int s = 0; s < 32; ++s)
                    part[s] += __shfl_xor_sync(0xffffffffu, part[s], off);
            if (l < 4) {
                #pragma unroll
                for (int nt = 0; nt < 16; ++nt) {
                    red[gw * 128 + nt * 8 + l * 2 + 0] = part[nt * 2 + 0];
                    red[gw * 128 + nt * 8 + l * 2 + 1] = part[nt * 2 + 1];
                }
            }
        }
        CPA_WAIT();
        GBAR(gid);

        // ---- final: combine 4 m-warps per n, store g_G ----
        {
            const int nl = gt >> 7, c = gt & 127;
            const float* rb = red + nl * 512 + c;
            g_G[(bc * 64 + n0 + nl) * 128 + c] = rb[0] + rb[128] + rb[256] + rb[384];
        }
    }
}

// =====================================================================
// Kernel C (HMMA): out = G @ Wv3 + asum * bv3. grid 32, one CTA = 2 bc
// =====================================================================
#define KC_W3   0u
#define KC_G    34816u
#define KC_MISC 69632u
#define KC_SMEM_BYTES (69632 + 1024)

__global__ __launch_bounds__(256, 1) void kC(Params P, float* __restrict__ out) {
    extern __shared__ char smc[];
    const int t = threadIdx.x;
    const int gw = t >> 5, l = t & 31;
    const int bc0 = blockIdx.x * 2;

    float* asum_s = reinterpret_cast<float*>(smc + KC_MISC);
    float* bv3_s  = asum_s + 128;
    unsigned short* Gt = reinterpret_cast<unsigned short*>(smc + KC_G);
    float* res = reinterpret_cast<float*>(smc);

    {
        const float4* s0 = reinterpret_cast<const float4*>(g_W3h);
        float4* d0 = reinterpret_cast<float4*>(smc + KC_W3);
        for (int i = t; i < 2176; i += 256) d0[i] = s0[i];
        if (t < 128) {
            asum_s[t] = g_asum[bc0 * 64 + t];
            bv3_s[t]  = P.p[17][t];
        }
    }

    {
        const int r = t >> 1, ac = t & 1;
        const float* src = g_G + bc0 * 8192 + r * 128 + ac * 64;
        unsigned short* ph = Gt + r * 136 + ac * 64;
        #pragma unroll 4
        for (int j = 0; j < 16; ++j) {
            float4 v = *reinterpret_cast<const float4*>(src + j * 4);
            __half2 h01 = __floats2half2_rn(v.x, v.y);
            __half2 h23 = __floats2half2_rn(v.z, v.w);
            uint2 vh;
            vh.x = *reinterpret_cast<unsigned*>(&h01);
            vh.y = *reinterpret_cast<unsigned*>(&h23);
            *reinterpret_cast<uint2*>(ph + j * 4) = vh;
        }
    }
    __syncthreads();

    const unsigned sbase = smem_u32(smc);
    const unsigned aAddr = sbase + KC_G + ((gw * 16 + (l & 15)) * 136) * 2 + (l >> 4) * 16;
    const unsigned bRow = (l & 7) + ((l >> 4) & 1) * 8;
    const unsigned bAddr = sbase + KC_W3 + (bRow * 136) * 2 + ((l >> 3) & 1) * 16;

    float acc[16][4];
    #pragma unroll
    for (int nt = 0; nt < 16; ++nt)
        #pragma unroll
        for (int j = 0; j < 4; ++j) acc[nt][j] = 0.f;

    #pragma unroll
    for (int ks = 0; ks < 8; ++ks) {
        unsigned ah[4];
        LDSM_X4(ah, aAddr + ks * 32);
        #pragma unroll
        for (int p = 0; p < 8; ++p) {
            unsigned bh[4];
            LDSM_X4(bh, bAddr + p * 4352 + ks * 32);
            MMA16816(acc[2*p],     ah, bh[0], bh[1]);
            MMA16816(acc[2*p + 1], ah, bh[2], bh[3]);
        }
    }
    __syncthreads();

    {
        const int qr = l >> 2, qc = l & 3;
        const int r0 = gw * 16 + qr, r1 = r0 + 8;
        #pragma unroll
        for (int nt = 0; nt < 16; ++nt) {
            #pragma unroll
            for (int jj = 0; jj < 2; ++jj) {
                int c = nt * 8 + qc * 2 + jj;
                res[r0 * 132 + c] = acc[nt][jj];
                res[r1 * 132 + c] = acc[nt][jj + 2];
            }
        }
    }
    __syncthreads();

    {
        float* ob = out + bc0 * 8192;
        #pragma unroll
        for (int k2 = 0; k2 < 16; ++k2) {
            int idx = k2 * 1024 + t * 4;
            int row = idx >> 7, col = idx & 127;
            float4 v = *reinterpret_cast<const float4*>(res + row * 132 + col);
            float as = asum_s[row];
            v.x = fmaf(as, bv3_s[col + 0], v.x);
            v.y = fmaf(as, bv3_s[col + 1], v.y);
            v.z = fmaf(as, bv3_s[col + 2], v.z);
            v.w = fmaf(as, bv3_s[col + 3], v.w);
            *reinterpret_cast<float4*>(ob + idx) = v;
        }
    }
}

// =====================================================================
extern "C" void kernel_launch(void* const* d_in, const int* in_sizes, int n_in,
                              void* d_out, int out_size) {
    (void)in_sizes; (void)n_in; (void)out_size;
    Params P;
    for (int i = 0; i < 24; ++i) P.p[i] = reinterpret_cast<const float*>(d_in[i]);

    const int SMEM_A1 = KA1_SMEM_FLOATS * 4;   // 221184
    const int SMEM_B  = KB_SMEM_BYTES;
    const int SMEM_C  = KC_SMEM_BYTES;

    cudaFuncSetAttribute(kA1, cudaFuncAttributeMaxDynamicSharedMemorySize, SMEM_A1);
    cudaFuncSetAttribute(kB,  cudaFuncAttributeMaxDynamicSharedMemorySize, SMEM_B);
    cudaFuncSetAttribute(kC,  cudaFuncAttributeMaxDynamicSharedMemorySize, SMEM_C);

    kA1<<<dim3(64, 3), NTHREADS, SMEM_A1>>>(P);
    kB <<<148, 512, SMEM_B>>>(P);
    kC <<<32, 256, SMEM_C>>>(P, reinterpret_cast<float*>(d_out));
}

// round 16
// speedup vs baseline: 1.5161x; 1.1408x over previous
#include <cuda_runtime.h>
#include <cuda_bf16.h>
#include <cuda_fp16.h>

#define NTHREADS 256

struct Params { const float* p[24]; };

// ---- scratch (static device globals; no allocation) ----
__device__ float g_keys   [64*64*128];
__device__ float g_queries[64*64*128];
__device__ float g_attn   [64*64*64];
__device__ float g_asum   [64*64];
__device__ float g_G      [64*64*128];
__device__ int   g_ready  [64];
// hq / (hk + bv1) as fp16
__device__ __align__(16) __half g_hqh[64*64*128];
__device__ __align__(16) __half g_hkh[64*64*128];
// Wv2^T / Wv3^T as [n][k], fp16, rows padded to 136 elems (272B)
__device__ __align__(16) unsigned short g_Wh [128*136];
__device__ __align__(16) unsigned short g_W3h[128*136];

__device__ __forceinline__ float tanha(float x) {
    float y;
    asm("tanh.approx.f32 %0, %1;" : "=f"(y) : "f"(x));
    return y;
}

__device__ __forceinline__ int colidx(int tx, int j) { return j < 4 ? tx*4 + j : 60 + tx*4 + j; }

__device__ __forceinline__ void zero_acc8(float acc[4][8]) {
    #pragma unroll
    for (int i = 0; i < 4; ++i)
        #pragma unroll
        for (int j = 0; j < 8; ++j) acc[i][j] = 0.f;
}

template<int K>
__device__ __forceinline__ void gemm_tile(const float* __restrict__ A, const float* __restrict__ W,
                                          float acc[4][8], int tx, int ty) {
    const int r0 = ty * 4;
    const int ca = tx * 4, cb = 64 + tx * 4;
    #pragma unroll 4
    for (int k = 0; k < K; ++k) {
        float aa[4];
        #pragma unroll
        for (int i = 0; i < 4; ++i) aa[i] = A[(r0 + i) * K + k];
        float4 b0 = *reinterpret_cast<const float4*>(W + k * 128 + ca);
        float4 b1 = *reinterpret_cast<const float4*>(W + k * 128 + cb);
        float bb[8] = {b0.x, b0.y, b0.z, b0.w, b1.x, b1.y, b1.z, b1.w};
        #pragma unroll
        for (int i = 0; i < 4; ++i)
            #pragma unroll
            for (int j = 0; j < 8; ++j)
                acc[i][j] = fmaf(aa[i], bb[j], acc[i][j]);
    }
}

__device__ __forceinline__ void store_row4(float* base, int row, int tx, const float v[8]) {
    *reinterpret_cast<float4*>(base + row * 128 + tx * 4)      = make_float4(v[0], v[1], v[2], v[3]);
    *reinterpret_cast<float4*>(base + row * 128 + 64 + tx * 4) = make_float4(v[4], v[5], v[6], v[7]);
}

__device__ __forceinline__ void store_row4_h(__half* base, int row, int tx, const float v[8]) {
    __half2 a01 = __floats2half2_rn(v[0], v[1]);
    __half2 a23 = __floats2half2_rn(v[2], v[3]);
    __half2 b01 = __floats2half2_rn(v[4], v[5]);
    __half2 b23 = __floats2half2_rn(v[6], v[7]);
    uint2 ua, ub;
    ua.x = *reinterpret_cast<unsigned*>(&a01); ua.y = *reinterpret_cast<unsigned*>(&a23);
    ub.x = *reinterpret_cast<unsigned*>(&b01); ub.y = *reinterpret_cast<unsigned*>(&b23);
    *reinterpret_cast<uint2*>(base + row * 128 + tx * 4)      = ua;
    *reinterpret_cast<uint2*>(base + row * 128 + 64 + tx * 4) = ub;
}

__device__ __forceinline__ unsigned smem_u32(const void* p) {
    unsigned a;
    asm("{ .reg .u64 t; cvta.to.shared.u64 t, %1; cvt.u32.u64 %0, t; }" : "=r"(a) : "l"(p));
    return a;
}

__device__ __forceinline__ unsigned prelu_h2(unsigned ua, unsigned ub, __half2 aV2, __half2 z2) {
    __half2 x = __hadd2(*reinterpret_cast<__half2*>(&ua), *reinterpret_cast<__half2*>(&ub));
    __half2 p = __hmul2(x, aV2);
    __half2 m = __hge2(x, z2);                       // 1.0 / 0.0 per half
    __half2 r = __hfma2(__hsub2(x, p), m, p);        // x if >=0 else a*x
    return *reinterpret_cast<unsigned*>(&r);
}

#define LDSM_X4(r, addr)                                                       \
    asm volatile("ldmatrix.sync.aligned.m8n8.x4.shared.b16 {%0,%1,%2,%3}, [%4];" \
        : "=r"((r)[0]), "=r"((r)[1]), "=r"((r)[2]), "=r"((r)[3]) : "r"(addr))

#define MMA16816(d, a, b0, b1)                                                 \
    asm volatile("mma.sync.aligned.m16n8k16.row.col.f32.f16.f16.f32 "          \
        "{%0,%1,%2,%3}, {%4,%5,%6,%7}, {%8,%9}, {%0,%1,%2,%3};"                \
        : "+f"((d)[0]), "+f"((d)[1]), "+f"((d)[2]), "+f"((d)[3])               \
        : "r"((a)[0]), "r"((a)[1]), "r"((a)[2]), "r"((a)[3]), "r"(b0), "r"(b1))

#define GBAR(gid)                                                              \
    asm volatile("bar.sync %0, %1;" :: "r"(gid), "r"(256u) : "memory")

#define CPA16(dst, src)                                                        \
    asm volatile("cp.async.cg.shared.global [%0], [%1], 16;"                   \
        :: "r"(dst), "l"((const void*)(src)) : "memory")
#define CPA_COMMIT() asm volatile("cp.async.commit_group;" ::: "memory")
#define CPA_WAIT()   asm volatile("cp.async.wait_group 0;" ::: "memory")

__device__ __forceinline__ void stage_async(unsigned dst, const float* src, int nfl, int t) {
    for (int i = t * 4; i < nfl; i += NTHREADS * 4)
        CPA16(dst + (unsigned)i * 4u, src + i);
}

// =====================================================================
// Kernel A1: keys / queries MLPs with double-buffered cp.async W
// prefetch. grid (64, 3): y=0 keys, y=1 queries, y=2 weight-convert+reset
// =====================================================================
// smem float offsets: X 0(6144) W0 6144(16384) W1 22528(16384) T1 38912(8192) T2 47104(8192)
#define KA1_SMEM_FLOATS 55296

__global__ __launch_bounds__(256) void kA1(Params P) {
    // ---- y==2: convert Wv2^T / Wv3^T to fp16 + reset ready flags ----
    if (blockIdx.y == 2) {
        int idx = blockIdx.x * 256 + threadIdx.x;   // 0..16383
        int n = idx >> 7, k = idx & 127;
        g_Wh [n * 136 + k] = __half_as_ushort(__float2half_rn(P.p[14][k * 128 + n]));
        g_W3h[n * 136 + k] = __half_as_ushort(__float2half_rn(P.p[16][k * 128 + n]));
        if (blockIdx.x == 0 && threadIdx.x < 64) g_ready[threadIdx.x] = 0;
        return;
    }

    extern __shared__ float sm[];
    float* X  = sm;
    float* W0 = sm + 6144;
    float* W1 = sm + 22528;
    float* T1 = sm + 38912;
    float* T2 = sm + 47104;
    const int t = threadIdx.x, tx = t & 15, ty = t >> 4;
    const int bc = blockIdx.x;
    const int r0 = ty * 4;
    const unsigned sb = smem_u32(sm);
    const unsigned uX = sb, uW0 = sb + 6144u * 4u, uW1 = sb + 22528u * 4u;
    float acc[4][8];

    if (blockIdx.y == 0) {
        // -------- keys path --------
        stage_async(uX, P.p[0] + bc * 6144, 6144, t);
        stage_async(uW0, P.p[2], 12288, t);
        CPA_COMMIT(); CPA_WAIT(); __syncthreads();

        stage_async(uW1, P.p[4], 16384, t); CPA_COMMIT();
        zero_acc8(acc);
        gemm_tile<96>(X, W0, acc, tx, ty);
        {
            const float aK = P.p[18][0];
            const float* bk1 = P.p[3];
            #pragma unroll
            for (int i = 0; i < 4; ++i) {
                float v[8];
                #pragma unroll
                for (int j = 0; j < 8; ++j) {
                    int c = colidx(tx, j);
                    float x = acc[i][j] + bk1[c];
                    v[j] = x >= 0.f ? x : aK * x;
                }
                store_row4(T1, r0 + i, tx, v);
            }
        }
        CPA_WAIT(); __syncthreads();

        stage_async(uW0, P.p[6], 16384, t); CPA_COMMIT();
        zero_acc8(acc);
        gemm_tile<128>(T1, W1, acc, tx, ty);
        {
            const float* bk2 = P.p[5];
            const float* gK  = P.p[20];
            const float* beK = P.p[21];
            #pragma unroll
            for (int i = 0; i < 4; ++i) {
                float v[8]; float s1 = 0.f, s2 = 0.f;
                #pragma unroll
                for (int j = 0; j < 8; ++j) {
                    int c = colidx(tx, j);
                    float x = tanha(acc[i][j] + bk2[c]);
                    v[j] = x; s1 += x; s2 += x * x;
                }
                #pragma unroll
                for (int off = 8; off >= 1; off >>= 1) {
                    s1 += __shfl_xor_sync(0xffffffffu, s1, off);
                    s2 += __shfl_xor_sync(0xffffffffu, s2, off);
                }
                float m  = s1 * (1.f / 128.f);
                float va = s2 * (1.f / 128.f) - m * m;
                float rs = rsqrtf(va + 1e-5f);
                #pragma unroll
                for (int j = 0; j < 8; ++j) {
                    int c = colidx(tx, j);
                    v[j] = (v[j] - m) * rs * gK[c] + beK[c];
                }
                store_row4(T2, r0 + i, tx, v);
            }
        }
        CPA_WAIT(); __syncthreads();

        stage_async(uW1, P.p[12] + 16384, 16384, t); CPA_COMMIT();
        zero_acc8(acc);
        gemm_tile<128>(T2, W0, acc, tx, ty);
        {
            const float* bk3 = P.p[7];
            float* kout = g_keys + bc * 8192;
            #pragma unroll
            for (int i = 0; i < 4; ++i) {
                float v[8];
                #pragma unroll
                for (int j = 0; j < 8; ++j) v[j] = acc[i][j] + bk3[colidx(tx, j)];
                store_row4(T1, r0 + i, tx, v);
                store_row4(kout, r0 + i, tx, v);
            }
        }
        CPA_WAIT(); __syncthreads();

        zero_acc8(acc);
        gemm_tile<128>(T1, W1, acc, tx, ty);
        {
            const float* bv1 = P.p[13];
            __half* hkout = g_hkh + bc * 8192;
            #pragma unroll
            for (int i = 0; i < 4; ++i) {
                float v[8];
                #pragma unroll
                for (int j = 0; j < 8; ++j) v[j] = acc[i][j] + bv1[colidx(tx, j)];
                store_row4_h(hkout, r0 + i, tx, v);
            }
        }
    } else {
        // -------- queries path --------
        stage_async(uX, P.p[1] + bc * 6144, 6144, t);
        stage_async(uW0, P.p[8], 12288, t);
        CPA_COMMIT(); CPA_WAIT(); __syncthreads();

        stage_async(uW1, P.p[10], 16384, t); CPA_COMMIT();
        zero_acc8(acc);
        gemm_tile<96>(X, W0, acc, tx, ty);
        {
            const float* bq1 = P.p[9];
            #pragma unroll
            for (int i = 0; i < 4; ++i) {
                float v[8];
                #pragma unroll
                for (int j = 0; j < 8; ++j) v[j] = tanha(acc[i][j] + bq1[colidx(tx, j)]);
                store_row4(T1, r0 + i, tx, v);
            }
        }
        CPA_WAIT(); __syncthreads();

        stage_async(uW0, P.p[12], 16384, t); CPA_COMMIT();
        zero_acc8(acc);
        gemm_tile<128>(T1, W1, acc, tx, ty);
        {
            const float* bq2 = P.p[11];
            float* qout = g_queries + bc * 8192;
            #pragma unroll
            for (int i = 0; i < 4; ++i) {
                float v[8];
                #pragma unroll
                for (int j = 0; j < 8; ++j) v[j] = acc[i][j] + bq2[colidx(tx, j)];
                store_row4(T2, r0 + i, tx, v);
                store_row4(qout, r0 + i, tx, v);
            }
        }
        CPA_WAIT(); __syncthreads();

        zero_acc8(acc);
        gemm_tile<128>(T2, W0, acc, tx, ty);
        {
            __half* hqout = g_hqh + bc * 8192;
            #pragma unroll
            for (int i = 0; i < 4; ++i) {
                float v[8];
                #pragma unroll
                for (int j = 0; j < 8; ++j) v[j] = acc[i][j];
                store_row4_h(hqout, r0 + i, tx, v);
            }
        }
    }
}

// =====================================================================
// Kernel B (persistent, dual-group HMMA, fp16 single chain, half2 build,
// cp.async prefetch, inlined kA2 with ready flags): grid 148 x 512.
// =====================================================================
#define KB_WH    0u                 // 34816 (fp16 W)
#define KB_A     34816u             // + group*34816 (Ahi)
#define KB_STG   104448u            // + group*17408: hq fp16 (16384) hk fp16 (512)
#define KB_CONST 139264u            // bv2s, gvs, bevs
#define KB_RED   140800u            // + group*4096
#define KB_SMEM_BYTES 148992

__global__ __launch_bounds__(512, 1) void kB(Params P) {
    extern __shared__ char smc[];
    const int t = threadIdx.x;
    const int wid = t >> 5, l = t & 31;
    const int group = wid >> 3;
    const int gt = t & 255;
    const int gw = wid & 7;
    const int gid = group + 1;

    // ---- inlined kA2: CTAs 0..63 compute softmax/attn for bc=blockIdx ----
    if (blockIdx.x < 64) {
        float* Kp = reinterpret_cast<float*>(smc);          // 64 x 129
        float* Q  = Kp + 8256;                              // 64 x 129
        float* L  = Q + 8256;                               // 64 x 65
        const int bcA = blockIdx.x;
        for (int i = t; i < 8192; i += 512) {
            int r = i >> 7, c = i & 127;
            Kp[r * 129 + c] = g_keys[bcA * 8192 + i];
            Q [r * 129 + c] = g_queries[bcA * 8192 + i];
        }
        __syncthreads();
        if (t < 256) {
            const int tx = t & 15, ty = t >> 4;
            float a2[4][4];
            #pragma unroll
            for (int i = 0; i < 4; ++i)
                #pragma unroll
                for (int j = 0; j < 4; ++j) a2[i][j] = 0.f;
            #pragma unroll 4
            for (int k = 0; k < 128; ++k) {
                float a[4], b[4];
                #pragma unroll
                for (int i = 0; i < 4; ++i) a[i] = Kp[(ty * 4 + i) * 129 + k];
                #pragma unroll
                for (int j = 0; j < 4; ++j) b[j] = Q[(tx * 4 + j) * 129 + k];
                #pragma unroll
                for (int i = 0; i < 4; ++i)
                    #pragma unroll
                    for (int j = 0; j < 4; ++j) a2[i][j] = fmaf(a[i], b[j], a2[i][j]);
            }
            #pragma unroll
            for (int i = 0; i < 4; ++i)
                #pragma unroll
                for (int j = 0; j < 4; ++j) L[(ty * 4 + i) * 65 + tx * 4 + j] = a2[i][j];
        }
        __syncthreads();
        if (t < 64) {
            int m = t;
            float mx = -1e30f;
            for (int n = 0; n < 64; ++n) mx = fmaxf(mx, L[n * 65 + m]);
            float s = 0.f;
            for (int n = 0; n < 64; ++n) { float e = expf(L[n * 65 + m] - mx); L[n * 65 + m] = e; s += e; }
            float inv = 1.f / s;
            for (int n = 0; n < 64; ++n) L[n * 65 + m] *= inv;
        }
        __syncthreads();
        if (t < 64) {
            int n = t; float s = 0.f;
            for (int m = 0; m < 64; ++m) {
                float v = L[n * 65 + m];
                g_attn[bcA * 4096 + n * 64 + m] = v;
                s += v;
            }
            g_asum[bcA * 64 + n] = s;
        }
        __threadfence();
        __syncthreads();
        if (t == 0) atomicExch(&g_ready[bcA], 1);
        __syncthreads();
    }

    float* bv2s = reinterpret_cast<float*>(smc + KB_CONST);
    float* gvs  = bv2s + 128;
    float* bevs = gvs + 128;
    float* red  = reinterpret_cast<float*>(smc + KB_RED + group * 4096u);
    __half* stgh = reinterpret_cast<__half*>(smc + KB_STG + group * 17408u);
    unsigned short* Ahi = reinterpret_cast<unsigned short*>(smc + KB_A + group * 34816u);

    // ---- one-time staging: W fp16 + const vectors ----
    {
        const float4* s0 = reinterpret_cast<const float4*>(g_Wh);
        float4* d0 = reinterpret_cast<float4*>(smc + KB_WH);
        for (int i = t; i < 2176; i += 512) d0[i] = s0[i];
        if (t < 128) {
            bv2s[t] = P.p[15][t];
            gvs[t]  = P.p[22][t];
            bevs[t] = P.p[23][t];
        }
    }

    const __half2 aV2 = __float2half2_rn(P.p[19][0]);
    const __half2 z2  = __float2half2_rn(0.f);
    const unsigned sbase = smem_u32(smc);
    const unsigned stgAddr = sbase + KB_STG + group * 17408u;
    const unsigned aAddr = sbase + KB_A + group * 34816u
                         + ((gw * 16 + (l & 15)) * 136) * 2 + (l >> 4) * 16;
    const unsigned bRow = (l & 7) + ((l >> 4) & 1) * 8;
    const unsigned bAddr = sbase + KB_WH + (bRow * 136) * 2 + ((l >> 3) & 1) * 16;

    const int qr = l >> 2, qc = l & 3;
    const int item0 = blockIdx.x * 2 + group;

    // ---- prologue prefetch: hq (16 KB) + hk (512 B) fp16 ----
    if (item0 < 2048) {
        int nbc = item0 >> 5, nn0 = (item0 & 31) * 2;
        const char* hsrc = reinterpret_cast<const char*>(g_hqh + nbc * 8192);
        #pragma unroll
        for (int k2 = 0; k2 < 4; ++k2) {
            unsigned u = (unsigned)(k2 * 256 + gt);
            CPA16(stgAddr + u * 16, hsrc + u * 16);
        }
        if (gt < 32)
            CPA16(stgAddr + 16384 + gt * 16,
                  reinterpret_cast<const char*>(g_hkh + (nbc * 64 + nn0) * 128) + gt * 16);
    }
    CPA_COMMIT();
    CPA_WAIT();
    __syncthreads();

    for (int item = item0; item < 2048; item += 296) {
        const int bc = item >> 5;
        const int n0 = (item & 31) * 2;

        // wait until this bc's attn is published (usually already set)
        if (gt == 0) {
            while (atomicAdd(&g_ready[bc], 0) == 0) { }
        }

        // ---- build A tile fp16 via half2 (no converts) ----
        {
            const int r = gt >> 1, ac = gt & 1;
            const int m = r & 63, nl = r >> 6;
            const __half* hqp = stgh + m * 128 + ac * 64;
            const __half* hkp = stgh + 8192 + nl * 128 + ac * 64;
            unsigned short* ph = Ahi + r * 136 + ac * 64;
            #pragma unroll
            for (int j = 0; j < 8; ++j) {
                uint4 va = *reinterpret_cast<const uint4*>(hqp + j * 8);
                uint4 vb = *reinterpret_cast<const uint4*>(hkp + j * 8);
                uint4 vo;
                vo.x = prelu_h2(va.x, vb.x, aV2, z2);
                vo.y = prelu_h2(va.y, vb.y, aV2, z2);
                vo.z = prelu_h2(va.z, vb.z, aV2, z2);
                vo.w = prelu_h2(va.w, vb.w, aV2, z2);
                *reinterpret_cast<uint4*>(ph + j * 8) = vo;
            }
        }
        GBAR(gid);

        // ---- prefetch next item ----
        {
            int nitem = item + 296;
            if (nitem < 2048) {
                int nbc = nitem >> 5, nn0 = (nitem & 31) * 2;
                const char* hsrc = reinterpret_cast<const char*>(g_hqh + nbc * 8192);
                #pragma unroll
                for (int k2 = 0; k2 < 4; ++k2) {
                    unsigned u = (unsigned)(k2 * 256 + gt);
                    CPA16(stgAddr + u * 16, hsrc + u * 16);
                }
                if (gt < 32)
                    CPA16(stgAddr + 16384 + gt * 16,
                          reinterpret_cast<const char*>(g_hkh + (nbc * 64 + nn0) * 128) + gt * 16);
            }
            CPA_COMMIT();
        }

        // ---- GEMM: 8 warps x (16m x 128n), K=128, single fp16 chain ----
        float acc[16][4];
        #pragma unroll
        for (int nt = 0; nt < 16; ++nt)
            #pragma unroll
            for (int j = 0; j < 4; ++j) acc[nt][j] = 0.f;

        #pragma unroll
        for (int ks = 0; ks < 8; ++ks) {
            unsigned ah[4];
            LDSM_X4(ah, aAddr + ks * 32);
            #pragma unroll
            for (int p = 0; p < 8; ++p) {
                unsigned bh[4];
                LDSM_X4(bh, bAddr + p * 4352 + ks * 32);
                MMA16816(acc[2*p],     ah, bh[0], bh[1]);
                MMA16816(acc[2*p + 1], ah, bh[2], bh[3]);
            }
        }

        // ---- epilogue: tanh.approx + folded LN + attn weighting ----
        {
            float s1a = 0.f, s2a = 0.f, s1b = 0.f, s2b = 0.f;
            #pragma unroll
            for (int nt = 0; nt < 16; ++nt) {
                int c0 = nt * 8 + qc * 2;
                float x0 = tanha(acc[nt][0] + bv2s[c0]);
                float x1 = tanha(acc[nt][1] + bv2s[c0 + 1]);
                float x2 = tanha(acc[nt][2] + bv2s[c0]);
                float x3 = tanha(acc[nt][3] + bv2s[c0 + 1]);
                acc[nt][0] = x0; acc[nt][1] = x1; acc[nt][2] = x2; acc[nt][3] = x3;
                s1a += x0 + x1; s2a += x0 * x0 + x1 * x1;
                s1b += x2 + x3; s2b += x2 * x2 + x3 * x3;
            }
            #pragma unroll
            for (int off = 1; off <= 2; off <<= 1) {
                s1a += __shfl_xor_sync(0xffffffffu, s1a, off);
                s2a += __shfl_xor_sync(0xffffffffu, s2a, off);
                s1b += __shfl_xor_sync(0xffffffffu, s1b, off);
                s2b += __shfl_xor_sync(0xffffffffu, s2b, off);
            }
            float mua = s1a * (1.f / 128.f);
            float rsa = rsqrtf(s2a * (1.f / 128.f) - mua * mua + 1e-5f);
            float mub = s1b * (1.f / 128.f);
            float rsb = rsqrtf(s2b * (1.f / 128.f) - mub * mub + 1e-5f);

            const int nn = n0 + (gw >> 2);
            const int m0 = (gw & 3) * 16 + qr;
            const float* ab = g_attn + bc * 4096 + nn * 64;
            float wa = __ldcg(ab + m0), wb = __ldcg(ab + m0 + 8);

            float aco0 = wa * rsa, aco1 = wb * rsb;
            float bsum = fmaf(aco0, mua, aco1 * mub);
            float ws = wa + wb;

            float part[32];
            #pragma unroll
            for (int nt = 0; nt < 16; ++nt) {
                #pragma unroll
                for (int jj = 0; jj < 2; ++jj) {
                    int c = nt * 8 + qc * 2 + jj;
                    float inner = fmaf(aco0, acc[nt][jj],
                                  fmaf(aco1, acc[nt][jj + 2], -bsum));
                    part[nt * 2 + jj] = fmaf(gvs[c], inner, bevs[c] * ws);
                }
            }
            #pragma unroll
            for (int off = 4; off <= 16; off <<= 1)
                #pragma unroll
                for (int s = 0; s < 32; ++s)
                    part[s] += __shfl_xor_sync(0xffffffffu, part[s], off);
            if (l < 4) {
                #pragma unroll
                for (int nt = 0; nt < 16; ++nt) {
                    red[gw * 128 + nt * 8 + l * 2 + 0] = part[nt * 2 + 0];
                    red[gw * 128 + nt * 8 + l * 2 + 1] = part[nt * 2 + 1];
                }
            }
        }
        CPA_WAIT();
        GBAR(gid);

        // ---- final: combine 4 m-warps per n, store g_G ----
        {
            const int nl = gt >> 7, c = gt & 127;
            const float* rb = red + nl * 512 + c;
            g_G[(bc * 64 + n0 + nl) * 128 + c] = rb[0] + rb[128] + rb[256] + rb[384];
        }
    }
}

// =====================================================================
// Kernel C (HMMA): out = G @ Wv3 + asum * bv3. grid 32, one CTA = 2 bc
// =====================================================================
#define KC_W3   0u
#define KC_G    34816u
#define KC_MISC 69632u
#define KC_SMEM_BYTES (69632 + 1024)

__global__ __launch_bounds__(256, 1) void kC(Params P, float* __restrict__ out) {
    extern __shared__ char smc[];
    const int t = threadIdx.x;
    const int gw = t >> 5, l = t & 31;
    const int bc0 = blockIdx.x * 2;

    float* asum_s = reinterpret_cast<float*>(smc + KC_MISC);
    float* bv3_s  = asum_s + 128;
    unsigned short* Gt = reinterpret_cast<unsigned short*>(smc + KC_G);
    float* res = reinterpret_cast<float*>(smc);

    {
        const float4* s0 = reinterpret_cast<const float4*>(g_W3h);
        float4* d0 = reinterpret_cast<float4*>(smc + KC_W3);
        for (int i = t; i < 2176; i += 256) d0[i] = s0[i];
        if (t < 128) {
            asum_s[t] = g_asum[bc0 * 64 + t];
            bv3_s[t]  = P.p[17][t];
        }
    }

    {
        const int r = t >> 1, ac = t & 1;
        const float* src = g_G + bc0 * 8192 + r * 128 + ac * 64;
        unsigned short* ph = Gt + r * 136 + ac * 64;
        #pragma unroll 4
        for (int j = 0; j < 16; ++j) {
            float4 v = *reinterpret_cast<const float4*>(src + j * 4);
            __half2 h01 = __floats2half2_rn(v.x, v.y);
            __half2 h23 = __floats2half2_rn(v.z, v.w);
            uint2 vh;
            vh.x = *reinterpret_cast<unsigned*>(&h01);
            vh.y = *reinterpret_cast<unsigned*>(&h23);
            *reinterpret_cast<uint2*>(ph + j * 4) = vh;
        }
    }
    __syncthreads();

    const unsigned sbase = smem_u32(smc);
    const unsigned aAddr = sbase + KC_G + ((gw * 16 + (l & 15)) * 136) * 2 + (l >> 4) * 16;
    const unsigned bRow = (l & 7) + ((l >> 4) & 1) * 8;
    const unsigned bAddr = sbase + KC_W3 + (bRow * 136) * 2 + ((l >> 3) & 1) * 16;

    float acc[16][4];
    #pragma unroll
    for (int nt = 0; nt < 16; ++nt)
        #pragma unroll
        for (int j = 0; j < 4; ++j) acc[nt][j] = 0.f;

    #pragma unroll
    for (int ks = 0; ks < 8; ++ks) {
        unsigned ah[4];
        LDSM_X4(ah, aAddr + ks * 32);
        #pragma unroll
        for (int p = 0; p < 8; ++p) {
            unsigned bh[4];
            LDSM_X4(bh, bAddr + p * 4352 + ks * 32);
            MMA16816(acc[2*p],     ah, bh[0], bh[1]);
            MMA16816(acc[2*p + 1], ah, bh[2], bh[3]);
        }
    }
    __syncthreads();

    {
        const int qr = l >> 2, qc = l & 3;
        const int r0 = gw * 16 + qr, r1 = r0 + 8;
        #pragma unroll
        for (int nt = 0; nt < 16; ++nt) {
            #pragma unroll
            for (int jj = 0; jj < 2; ++jj) {
                int c = nt * 8 + qc * 2 + jj;
                res[r0 * 132 + c] = acc[nt][jj];
                res[r1 * 132 + c] = acc[nt][jj + 2];
            }
        }
    }
    __syncthreads();

    {
        float* ob = out + bc0 * 8192;
        #pragma unroll
        for (int k2 = 0; k2 < 16; ++k2) {
            int idx = k2 * 1024 + t * 4;
            int row = idx >> 7, col = idx & 127;
            float4 v = *reinterpret_cast<const float4*>(res + row * 132 + col);
            float as = asum_s[row];
            v.x = fmaf(as, bv3_s[col + 0], v.x);
            v.y = fmaf(as, bv3_s[col + 1], v.y);
            v.z = fmaf(as, bv3_s[col + 2], v.z);
            v.w = fmaf(as, bv3_s[col + 3], v.w);
            *reinterpret_cast<float4*>(ob + idx) = v;
        }
    }
}

// =====================================================================
extern "C" void kernel_launch(void* const* d_in, const int* in_sizes, int n_in,
                              void* d_out, int out_size) {
    (void)in_sizes; (void)n_in; (void)out_size;
    Params P;
    for (int i = 0; i < 24; ++i) P.p[i] = reinterpret_cast<const float*>(d_in[i]);

    const int SMEM_A1 = KA1_SMEM_FLOATS * 4;   // 221184
    const int SMEM_B  = KB_SMEM_BYTES;
    const int SMEM_C  = KC_SMEM_BYTES;

    cudaFuncSetAttribute(kA1, cudaFuncAttributeMaxDynamicSharedMemorySize, SMEM_A1);
    cudaFuncSetAttribute(kB,  cudaFuncAttributeMaxDynamicSharedMemorySize, SMEM_B);
    cudaFuncSetAttribute(kC,  cudaFuncAttributeMaxDynamicSharedMemorySize, SMEM_C);

    kA1<<<dim3(64, 3), NTHREADS, SMEM_A1>>>(P);
    kB <<<148, 512, SMEM_B>>>(P);
    kC <<<32, 256, SMEM_C>>>(P, reinterpret_cast<float*>(d_out));
}